// round 2
// baseline (speedup 1.0000x reference)
#include <cuda_runtime.h>
#include <cuda_bf16.h>

// Problem dims (fixed)
#define Bq 512
#define Tq 128
#define Iq 512
#define Hq 512
#define Cq 97
#define Sq 26

// ---------------- scratch (static device globals; no allocations) ----------
__device__ float g_feat[(size_t)Bq * Tq * Hq];     // 134 MB: batch_H @ W_feat^T
__device__ float g_h[Bq * Hq];
__device__ float g_c[Bq * Hq];
__device__ float g_hp[Bq * Hq];
__device__ float g_x[Bq * (Iq + Hq)];              // [ctx | h] per row, ld = 1024
__device__ float g_gates[Bq * 4 * Hq];
__device__ float g_Wg[4 * Hq * (Iq + Hq)];         // [2048 x 1024] = [W_ih[:, :I] | W_hh]

// ---------------- fast transcendentals (fp32, ~2ulp via EX2) ----------------
__device__ __forceinline__ float fast_sigmoid(float x) {
    return __fdividef(1.f, 1.f + __expf(-x));
}
__device__ __forceinline__ float fast_tanh(float x) {
    float xc = fminf(fmaxf(x, -15.f), 15.f);
    float e = __expf(2.f * xc);
    return __fdividef(e - 1.f, e + 1.f);
}

// ---------------- init: zero h, c, and h-half of x --------------------------
__global__ void init_kernel() {
    int idx = blockIdx.x * blockDim.x + threadIdx.x;   // 0..B*H-1 (1024x256)
    g_h[idx] = 0.f;
    g_c[idx] = 0.f;
    int b = idx >> 9, hh = idx & 511;
    g_x[b * (Iq + Hq) + Iq + hh] = 0.f;
}

// ---------------- build concatenated gate weight [2048 x 1024] --------------
__global__ void build_wg_kernel(const float* __restrict__ W_ih,
                                const float* __restrict__ W_hh) {
    int idx = blockIdx.x * blockDim.x + threadIdx.x;   // 0..2048*1024-1
    int j = idx >> 10, k = idx & 1023;
    g_Wg[idx] = (k < Iq) ? W_ih[j * (Iq + Cq) + k] : W_hh[j * Hq + (k - Iq)];
}

// ---------------- generic SGEMM: C[M,N] = A[M,K] * B[N,K]^T (both K-major) ---
// BMN x BMN tile, BK=16, 256 threads, TMN x TMN microtile per thread.
template <int BMN, int TMN>
__global__ __launch_bounds__(256)
void gemm_nt(const float* __restrict__ A, const float* __restrict__ Bm,
             float* __restrict__ C, int K, int lda, int ldb, int ldc,
             int accum, int b4ok) {
    __shared__ float As[16][BMN];
    __shared__ float Bs[16][BMN];
    const int tid = threadIdx.x;
    const int tx = tid & 15;
    const int ty = tid >> 4;
    const int row0 = blockIdx.y * BMN;
    const int col0 = blockIdx.x * BMN;

    float acc[TMN][TMN];
#pragma unroll
    for (int i = 0; i < TMN; i++)
#pragma unroll
        for (int j = 0; j < TMN; j++) acc[i][j] = 0.f;

    for (int k0 = 0; k0 < K; k0 += 16) {
#pragma unroll
        for (int u = 0; u < BMN / 64; u++) {
            int e = tid + u * 256;
            int r = e >> 2;
            int kk = (e & 3) << 2;
            float4 av = *reinterpret_cast<const float4*>(
                A + (size_t)(row0 + r) * lda + k0 + kk);
            As[kk + 0][r] = av.x; As[kk + 1][r] = av.y;
            As[kk + 2][r] = av.z; As[kk + 3][r] = av.w;
            const float* bp = Bm + (size_t)(col0 + r) * ldb + k0 + kk;
            float4 bv;
            if (b4ok) {
                bv = *reinterpret_cast<const float4*>(bp);
            } else {
                bv.x = bp[0]; bv.y = bp[1]; bv.z = bp[2]; bv.w = bp[3];
            }
            Bs[kk + 0][r] = bv.x; Bs[kk + 1][r] = bv.y;
            Bs[kk + 2][r] = bv.z; Bs[kk + 3][r] = bv.w;
        }
        __syncthreads();
#pragma unroll
        for (int k = 0; k < 16; k++) {
            float a[TMN], b[TMN];
#pragma unroll
            for (int q = 0; q < TMN / 4; q++) {
                *reinterpret_cast<float4*>(&a[q * 4]) =
                    *reinterpret_cast<const float4*>(&As[k][ty * TMN + q * 4]);
                *reinterpret_cast<float4*>(&b[q * 4]) =
                    *reinterpret_cast<const float4*>(&Bs[k][tx * TMN + q * 4]);
            }
#pragma unroll
            for (int i = 0; i < TMN; i++)
#pragma unroll
                for (int j = 0; j < TMN; j++)
                    acc[i][j] = fmaf(a[i], b[j], acc[i][j]);
        }
        __syncthreads();
    }
#pragma unroll
    for (int i = 0; i < TMN; i++) {
        int r = row0 + ty * TMN + i;
#pragma unroll
        for (int j = 0; j < TMN; j++) {
            int c = col0 + tx * TMN + j;
            float v = acc[i][j];
            if (accum) v += C[(size_t)r * ldc + c];
            C[(size_t)r * ldc + c] = v;
        }
    }
}

// ---------------- fused attention: e -> softmax -> ctx (one block per b) -----
__global__ __launch_bounds__(256)
void attn_kernel(const float* __restrict__ batch_H,
                 const float* __restrict__ b_hid,
                 const float* __restrict__ w_score) {
    __shared__ float hp_s[Hq];
    __shared__ float ws[Hq];
    __shared__ float e_s[Tq];

    const int b = blockIdx.x;
    const int tid = threadIdx.x;
    const int warp = tid >> 5, lane = tid & 31;

    for (int i = tid; i < Hq; i += 256) {
        hp_s[i] = g_hp[b * Hq + i] + b_hid[i];
        ws[i] = w_score[i];
    }
    __syncthreads();

    // e[t] = sum_h tanh(feat[b,t,h] + hp[h]) * w_score[h]
    const float* fb = g_feat + (size_t)b * Tq * Hq;
    for (int t = warp; t < Tq; t += 8) {
        const float* fr = fb + (size_t)t * Hq;
        float s = 0.f;
#pragma unroll 4
        for (int h = lane; h < Hq; h += 32)
            s += fast_tanh(fr[h] + hp_s[h]) * ws[h];
#pragma unroll
        for (int o = 16; o; o >>= 1) s += __shfl_xor_sync(0xffffffffu, s, o);
        if (lane == 0) e_s[t] = s;
    }
    __syncthreads();

    // softmax over T=128 (warp 0)
    if (warp == 0) {
        float v0 = e_s[lane], v1 = e_s[lane + 32];
        float v2 = e_s[lane + 64], v3 = e_s[lane + 96];
        float m = fmaxf(fmaxf(v0, v1), fmaxf(v2, v3));
#pragma unroll
        for (int o = 16; o; o >>= 1) m = fmaxf(m, __shfl_xor_sync(0xffffffffu, m, o));
        float x0 = __expf(v0 - m), x1 = __expf(v1 - m);
        float x2 = __expf(v2 - m), x3 = __expf(v3 - m);
        float sum = x0 + x1 + x2 + x3;
#pragma unroll
        for (int o = 16; o; o >>= 1) sum += __shfl_xor_sync(0xffffffffu, sum, o);
        float inv = __fdividef(1.f, sum);
        e_s[lane] = x0 * inv;       e_s[lane + 32] = x1 * inv;
        e_s[lane + 64] = x2 * inv;  e_s[lane + 96] = x3 * inv;
    }
    __syncthreads();

    // ctx[i] = sum_t alpha[t] * batch_H[b,t,i]  -> x[b, 0:I]
    const float* Hb = batch_H + (size_t)b * Tq * Iq;
    for (int i = tid; i < Iq; i += 256) {
        float a0 = 0.f;
#pragma unroll 4
        for (int t = 0; t < Tq; t++)
            a0 = fmaf(e_s[t], Hb[(size_t)t * Iq + i], a0);
        g_x[b * (Iq + Hq) + i] = a0;
    }
}

// ---------------- LSTM elementwise (one thread per (b, hh)) ------------------
__global__ __launch_bounds__(256)
void lstm_kernel(const float* __restrict__ b_ih, const float* __restrict__ b_hh,
                 const float* __restrict__ W_ih, const int* __restrict__ text,
                 int s) {
    int idx = blockIdx.x * blockDim.x + threadIdx.x;  // 0..B*H-1
    int b = idx >> 9, hh = idx & 511;
    int tc = text[b * Sq + s];
    const float* g = g_gates + (size_t)b * 4 * Hq;
    const float* wcol = W_ih + Iq + tc;  // one-hot column, row stride I+C = 609

    float gi = g[hh]            + b_ih[hh]            + b_hh[hh]            + wcol[(size_t)(hh)            * (Iq + Cq)];
    float gf = g[Hq + hh]       + b_ih[Hq + hh]       + b_hh[Hq + hh]       + wcol[(size_t)(Hq + hh)       * (Iq + Cq)];
    float gg = g[2 * Hq + hh]   + b_ih[2 * Hq + hh]   + b_hh[2 * Hq + hh]   + wcol[(size_t)(2 * Hq + hh)   * (Iq + Cq)];
    float go = g[3 * Hq + hh]   + b_ih[3 * Hq + hh]   + b_hh[3 * Hq + hh]   + wcol[(size_t)(3 * Hq + hh)   * (Iq + Cq)];

    float c = g_c[idx];
    float c2 = fast_sigmoid(gf) * c + fast_sigmoid(gi) * fast_tanh(gg);
    float h2 = fast_sigmoid(go) * fast_tanh(c2);
    g_c[idx] = c2;
    g_h[idx] = h2;
    g_x[b * (Iq + Hq) + Iq + hh] = h2;
}

// ---------------- generator: probs[b,s,:] = h @ W_gen^T + b_gen --------------
__global__ __launch_bounds__(256)
void gen_kernel(const float* __restrict__ W_gen, const float* __restrict__ b_gen,
                float* __restrict__ out, int s) {
    __shared__ float hs[Hq];
    const int b = blockIdx.x;
    const int tid = threadIdx.x;
    const int warp = tid >> 5, lane = tid & 31;
    for (int i = tid; i < Hq; i += 256) hs[i] = g_h[b * Hq + i];
    __syncthreads();
    for (int c = warp; c < Cq; c += 8) {
        const float* w = W_gen + (size_t)c * Hq;
        float sum = 0.f;
#pragma unroll 4
        for (int h = lane; h < Hq; h += 32) sum = fmaf(hs[h], w[h], sum);
#pragma unroll
        for (int o = 16; o; o >>= 1) sum += __shfl_xor_sync(0xffffffffu, sum, o);
        if (lane == 0) out[((size_t)b * Sq + s) * Cq + c] = sum + b_gen[c];
    }
}

// ---------------- launch ----------------------------------------------------
extern "C" void kernel_launch(void* const* d_in, const int* in_sizes, int n_in,
                              void* d_out, int out_size) {
    const float* batch_H = (const float*)d_in[0];
    const int*   text    = (const int*)d_in[1];
    const float* W_feat  = (const float*)d_in[2];
    const float* W_hid   = (const float*)d_in[3];
    const float* b_hid   = (const float*)d_in[4];
    const float* w_score = (const float*)d_in[5];
    const float* W_ih    = (const float*)d_in[6];
    const float* W_hh    = (const float*)d_in[7];
    const float* b_ih    = (const float*)d_in[8];
    const float* b_hh    = (const float*)d_in[9];
    const float* W_gen   = (const float*)d_in[10];
    const float* b_gen   = (const float*)d_in[11];
    float* out = (float*)d_out;

    float *p_feat, *p_h, *p_hp, *p_x, *p_gates, *p_Wg;
    cudaGetSymbolAddress((void**)&p_feat,  g_feat);
    cudaGetSymbolAddress((void**)&p_h,     g_h);
    cudaGetSymbolAddress((void**)&p_hp,    g_hp);
    cudaGetSymbolAddress((void**)&p_x,     g_x);
    cudaGetSymbolAddress((void**)&p_gates, g_gates);
    cudaGetSymbolAddress((void**)&p_Wg,    g_Wg);

    init_kernel<<<(Bq * Hq) / 256, 256>>>();
    build_wg_kernel<<<(4 * Hq * (Iq + Hq)) / 256, 256>>>(W_ih, W_hh);

    // feat = batch_H @ W_feat^T  : [65536, 512] x [512, 512]^T
    gemm_nt<128, 8><<<dim3(Hq / 128, (Bq * Tq) / 128), 256>>>(
        batch_H, W_feat, p_feat, Iq, Iq, Iq, Hq, /*accum=*/0, /*b4ok=*/1);

    for (int s = 0; s < Sq; s++) {
        // hp = h @ W_hid^T   : [512,512,512]
        gemm_nt<64, 4><<<dim3(Hq / 64, Bq / 64), 256>>>(
            p_h, W_hid, p_hp, Hq, Hq, Hq, Hq, 0, 1);

        // attention score + softmax + context -> x[:, 0:I]
        attn_kernel<<<Bq, 256>>>(batch_H, b_hid, w_score);

        // gates = [ctx|h] @ Wg^T : [512, 2048, 1024]
        gemm_nt<64, 4><<<dim3((4 * Hq) / 64, Bq / 64), 256>>>(
            p_x, p_Wg, p_gates, Iq + Hq, Iq + Hq, Iq + Hq, 4 * Hq, 0, 1);

        // LSTM cell update (+ biases + one-hot column of W_ih)
        lstm_kernel<<<(Bq * Hq) / 256, 256>>>(b_ih, b_hh, W_ih, text, s);

        // output probs for this step
        gen_kernel<<<Bq, 256>>>(W_gen, b_gen, out, s);
    }
}

// round 4
// speedup vs baseline: 1.9237x; 1.9237x over previous
#include <cuda_runtime.h>
#include <cuda_fp16.h>
#include <cuda_bf16.h>
#include <cstdint>

// Problem dims (fixed)
#define Bq 512
#define Tq 128
#define Iq 512
#define Hq 512
#define Cq 97
#define Sq 26
#define NC1 2560   // hp(512) + gates_h(2048)
#define NG  2048   // 4H

#if defined(__CUDA_ARCH_FEAT_SM103_ALL) || defined(__CUDA_ARCH_FEAT_SM100_ALL)
#define HAS_TCGEN05 1
#else
#define HAS_TCGEN05 0
#endif

// ---------------- scratch (static device globals; no allocations) ----------
__device__ __align__(16) __nv_bfloat16 g_bH_hi[(size_t)Bq * Tq * Iq];  // 67MB
__device__ __align__(16) __nv_bfloat16 g_bH_lo[(size_t)Bq * Tq * Iq];  // 67MB
__device__ __align__(16) __half        g_bH16[(size_t)Bq * Tq * Iq];   // 67MB (ctx pass)
__device__ __align__(16) __half        g_feat[(size_t)Bq * Tq * Hq];   // 67MB fp16
__device__ __align__(16) float         g_h[Bq * Hq];
__device__ __align__(16) float         g_c[Bq * Hq];
__device__ __align__(16) __nv_bfloat16 g_h_hi[Bq * Hq];
__device__ __align__(16) __nv_bfloat16 g_h_lo[Bq * Hq];
__device__ __align__(16) __nv_bfloat16 g_ctx_hi[Bq * Iq];
__device__ __align__(16) __nv_bfloat16 g_ctx_lo[Bq * Iq];
__device__ __align__(16) float         g_y1[Bq * NC1];                  // [hp | gates_h]
__device__ __align__(16) float         g_gates[Bq * NG];
__device__ __align__(16) __nv_bfloat16 g_Wc_hi[NC1 * Hq];               // [W_hid; W_hh]
__device__ __align__(16) __nv_bfloat16 g_Wc_lo[NC1 * Hq];
__device__ __align__(16) __nv_bfloat16 g_Wih_hi[NG * Iq];               // W_ih[:, :I]
__device__ __align__(16) __nv_bfloat16 g_Wih_lo[NG * Iq];
__device__ __align__(16) __nv_bfloat16 g_Wf_hi[Hq * Iq];
__device__ __align__(16) __nv_bfloat16 g_Wf_lo[Hq * Iq];

// ---------------- helpers ---------------------------------------------------
__device__ __forceinline__ float fast_sigmoid(float x) {
    return __fdividef(1.f, 1.f + __expf(-x));
}
__device__ __forceinline__ float fast_tanh(float x) {
    float xc = fminf(fmaxf(x, -15.f), 15.f);
    float e = __expf(2.f * xc);
    return __fdividef(e - 1.f, e + 1.f);
}
__device__ __forceinline__ void split2(float a, __nv_bfloat16* hi, __nv_bfloat16* lo) {
    __nv_bfloat16 h = __float2bfloat16(a);
    *hi = h;
    *lo = __float2bfloat16(a - __bfloat162float(h));
}
__device__ __forceinline__ uint32_t s2u(const void* p) {
    uint32_t a;
    asm("{ .reg .u64 t; cvta.to.shared.u64 t, %1; cvt.u32.u64 %0, t; }" : "=r"(a) : "l"(p));
    return a;
}
__device__ __forceinline__ void cpa16(uint32_t s, const void* g) {
    asm volatile("cp.async.cg.shared.global [%0], [%1], 16;" :: "r"(s), "l"(g));
}

#if HAS_TCGEN05
__device__ __forceinline__ uint32_t elect1() {
    uint32_t p;
    asm volatile("{ .reg .pred p; elect.sync _|p, 0xFFFFFFFF; selp.b32 %0, 1, 0, p; }" : "=r"(p));
    return p;
}
__device__ __forceinline__ void mbar_wait(uint32_t a, uint32_t ph) {
    asm volatile(
        "{\n\t.reg .pred P;\n"
        "LW%=:\n\t"
        "mbarrier.try_wait.parity.acquire.cta.shared::cta.b64 P, [%0], %1, 0x989680;\n\t"
        "@!P bra.uni LW%=;\n\t}"
        :: "r"(a), "r"(ph) : "memory");
}
// cg1 SS bf16 MMA, fp32 accum
__device__ __forceinline__ void mma_ss(uint32_t d, uint64_t a, uint64_t b, uint32_t idesc, bool en) {
    uint32_t e = en ? 1u : 0u;
    asm volatile(
        "{\n\t.reg .pred p;\n\t"
        "setp.ne.u32 p, %5, 0;\n\t"
        "tcgen05.mma.cta_group::1.kind::f16 [%0], %1, %2, %3, {%4, %4, %4, %4}, p;\n\t}"
        :: "r"(d), "l"(a), "l"(b), "r"(idesc), "r"(0u), "r"(e) : "memory");
}
__device__ __forceinline__ void ldtm32(uint32_t* r, uint32_t a) {
    asm volatile(
        "tcgen05.ld.sync.aligned.32x32b.x32.b32 "
        "{%0, %1, %2, %3, %4, %5, %6, %7, %8, %9, %10, %11, %12, %13, %14, %15, "
        "%16, %17, %18, %19, %20, %21, %22, %23, %24, %25, %26, %27, %28, %29, %30, %31}, [%32];"
        : "=r"(r[0]), "=r"(r[1]), "=r"(r[2]), "=r"(r[3]), "=r"(r[4]), "=r"(r[5]), "=r"(r[6]), "=r"(r[7]),
          "=r"(r[8]), "=r"(r[9]), "=r"(r[10]), "=r"(r[11]), "=r"(r[12]), "=r"(r[13]), "=r"(r[14]), "=r"(r[15]),
          "=r"(r[16]), "=r"(r[17]), "=r"(r[18]), "=r"(r[19]), "=r"(r[20]), "=r"(r[21]), "=r"(r[22]), "=r"(r[23]),
          "=r"(r[24]), "=r"(r[25]), "=r"(r[26]), "=r"(r[27]), "=r"(r[28]), "=r"(r[29]), "=r"(r[30]), "=r"(r[31])
        : "r"(a));
}
#endif

static constexpr uint64_t DESCBASE =
    (uint64_t(2) << 61) | (uint64_t(1) << 46) | (uint64_t(64) << 32) | (uint64_t(1) << 16); // SW128 K-major
static constexpr uint32_t IDESC_128x128 = 0x8200490u; // F32 acc, bf16 A/B, M=128, N=128
static constexpr int GEMM_SMEM = 64 * 1024 + 1024;

// ---------------- prep kernels ----------------------------------------------
__global__ void init_kernel() {
    int i = blockIdx.x * blockDim.x + threadIdx.x;   // B*H
    g_h[i] = 0.f; g_c[i] = 0.f;
    g_h_hi[i] = __float2bfloat16(0.f); g_h_lo[i] = __float2bfloat16(0.f);
}
__global__ void prep_bh(const float* __restrict__ bH) {
    size_t i = (size_t)blockIdx.x * blockDim.x + threadIdx.x;  // B*T*I
    float v = bH[i];
    split2(v, &g_bH_hi[i], &g_bH_lo[i]);
    g_bH16[i] = __float2half(v);
}
__global__ void prep_wc(const float* __restrict__ W_hid, const float* __restrict__ W_hh) {
    int i = blockIdx.x * blockDim.x + threadIdx.x;  // NC1*512
    int j = i >> 9, k = i & 511;
    float v = (j < Hq) ? W_hid[j * Hq + k] : W_hh[(j - Hq) * Hq + k];
    split2(v, &g_Wc_hi[i], &g_Wc_lo[i]);
}
__global__ void prep_wih(const float* __restrict__ W_ih) {
    int i = blockIdx.x * blockDim.x + threadIdx.x;  // NG*512
    int j = i >> 9, k = i & 511;
    split2(W_ih[j * (Iq + Cq) + k], &g_Wih_hi[i], &g_Wih_lo[i]);
}
__global__ void prep_wf(const float* __restrict__ W_feat) {
    int i = blockIdx.x * blockDim.x + threadIdx.x;  // H*I
    split2(W_feat[i], &g_Wf_hi[i], &g_Wf_lo[i]);
}

// ---------------- split-bf16 GEMM: C[M,N] = A[M,K] @ B[N,K]^T ---------------
// MODE 0: fp32 out.  MODE 1: fp32 out + addsrc[r*ldadd + addoff + col].  MODE 2: fp16 out.
// sm_103a path: tcgen05.  Plain sm_103 fallback: SIMT FFMA (correct, slower).
template <int MODE>
__global__ __launch_bounds__(256)
void gemm_tc(const __nv_bfloat16* __restrict__ Ahi, const __nv_bfloat16* __restrict__ Alo,
             const __nv_bfloat16* __restrict__ Bhi, const __nv_bfloat16* __restrict__ Blo,
             int K, void* Cout, int ldc,
             const float* __restrict__ addsrc, int ldadd, int addoff) {
#if HAS_TCGEN05
    extern __shared__ char dsm[];
    __shared__ uint32_t s_tmem[2];
    __shared__ __align__(8) uint64_t s_mbar;
    const int tid = threadIdx.x, wid = tid >> 5, lane = tid & 31;
    const int row0 = blockIdx.y * 128, col0 = blockIdx.x * 128;

    uint32_t ctrl = s2u(s_tmem);
    uint32_t mbar = s2u(&s_mbar);
    if (wid == 0)
        asm volatile("tcgen05.alloc.cta_group::1.sync.aligned.shared::cta.b32 [%0], %1;"
                     :: "r"(ctrl), "r"(128) : "memory");
    if (tid == 0)
        asm volatile("mbarrier.init.shared.b64 [%0], %1;" :: "r"(mbar), "r"(1) : "memory");
    __syncthreads();
    const uint32_t tmem = s_tmem[0];

    uint32_t tile = (s2u(dsm) + 1023u) & ~1023u;
    const uint32_t sA0 = tile, sA1 = tile + 16384, sB0 = tile + 32768, sB1 = tile + 49152;
    const uint64_t dA0 = DESCBASE | ((sA0 >> 4) & 0x3FFF);
    const uint64_t dA1 = DESCBASE | ((sA1 >> 4) & 0x3FFF);
    const uint64_t dB0 = DESCBASE | ((sB0 >> 4) & 0x3FFF);
    const uint64_t dB1 = DESCBASE | ((sB1 >> 4) & 0x3FFF);

    const int nchunk = K >> 6;
    for (int c = 0; c < nchunk; c++) {
        // load A/B hi/lo 128x64 bf16 tiles, SW128-swizzled, via cp.async (16B each)
#pragma unroll
        for (int s4 = 0; s4 < 4; s4++) {
            int v = tid + (s4 << 8);          // 0..1023
            int r = v >> 3;
            int c8 = (v & 7) << 3;
            uint32_t so = (uint32_t)(r * 128 + c8 * 2);
            so ^= (so >> 3) & 0x70;
            size_t ga = (size_t)(row0 + r) * K + (size_t)c * 64 + c8;
            size_t gb = (size_t)(col0 + r) * K + (size_t)c * 64 + c8;
            cpa16(sA0 + so, Ahi + ga);
            cpa16(sA1 + so, Alo + ga);
            cpa16(sB0 + so, Bhi + gb);
            cpa16(sB1 + so, Blo + gb);
        }
        asm volatile("cp.async.commit_group;" ::: "memory");
        asm volatile("cp.async.wait_group 0;" ::: "memory");
        asm volatile("fence.proxy.async.shared::cta;" ::: "memory");
        __syncthreads();

        if (wid == 0 && elect1()) {
            // 3-term split: hi*hi, hi*lo, lo*hi  (4 k-steps of 16 each)
#pragma unroll
            for (int ks = 0; ks < 4; ks++)
                mma_ss(tmem, dA0 + ks * 2, dB0 + ks * 2, IDESC_128x128, !(c == 0 && ks == 0));
#pragma unroll
            for (int ks = 0; ks < 4; ks++)
                mma_ss(tmem, dA0 + ks * 2, dB1 + ks * 2, IDESC_128x128, true);
#pragma unroll
            for (int ks = 0; ks < 4; ks++)
                mma_ss(tmem, dA1 + ks * 2, dB0 + ks * 2, IDESC_128x128, true);
            asm volatile(
                "tcgen05.commit.cta_group::1.mbarrier::arrive::one.shared::cluster.b64 [%0];"
                :: "r"(mbar) : "memory");
        }
        mbar_wait(mbar, (uint32_t)(c & 1));
    }
    asm volatile("tcgen05.fence::after_thread_sync;" ::: "memory");

    // epilogue: 8 warps, warp w -> subpartition (w&3) rows, col-half (w>>2)
    uint32_t regs[64];
    const int ch = wid >> 2, sp = wid & 3;
    ldtm32(regs, tmem + ch * 64);
    ldtm32(regs + 32, tmem + ch * 64 + 32);
    asm volatile("tcgen05.wait::ld.sync.aligned;" ::: "memory");
    asm volatile("tcgen05.fence::before_thread_sync;" ::: "memory");
    const int r = row0 + sp * 32 + lane;
    const int cb = col0 + ch * 64;
    if (MODE == 2) {
        __half* C = (__half*)Cout;
#pragma unroll
        for (int j = 0; j < 64; j += 2) {
            __half2 h2 = __floats2half2_rn(__uint_as_float(regs[j]), __uint_as_float(regs[j + 1]));
            *(__half2*)(C + (size_t)r * ldc + cb + j) = h2;
        }
    } else {
        float* C = (float*)Cout;
#pragma unroll
        for (int j = 0; j < 64; j += 4) {
            float4 v;
            v.x = __uint_as_float(regs[j]);
            v.y = __uint_as_float(regs[j + 1]);
            v.z = __uint_as_float(regs[j + 2]);
            v.w = __uint_as_float(regs[j + 3]);
            if (MODE == 1) {
                const float* ap = addsrc + (size_t)r * ldadd + addoff + cb + j;
                v.x += ap[0]; v.y += ap[1]; v.z += ap[2]; v.w += ap[3];
            }
            *(float4*)(C + (size_t)r * ldc + cb + j) = v;
        }
    }
    __syncthreads();
    if (wid == 0) {
        if (lane == 0)
            asm volatile("mbarrier.inval.shared.b64 [%0];" :: "r"(mbar) : "memory");
        asm volatile("tcgen05.relinquish_alloc_permit.cta_group::1.sync.aligned;");
        asm volatile("tcgen05.dealloc.cta_group::1.sync.aligned.b32 %0, %1;" :: "r"(tmem), "r"(128));
    }
#else
    // -------- SIMT fallback (plain sm_103 compilation unit): correct path ----
    __shared__ float As[16][128];
    __shared__ float Bs[16][128];
    const int tid = threadIdx.x;
    const int tx = tid & 15, ty = tid >> 4;
    const int row0 = blockIdx.y * 128, col0 = blockIdx.x * 128;

    float acc[8][8];
#pragma unroll
    for (int i = 0; i < 8; i++)
#pragma unroll
        for (int j = 0; j < 8; j++) acc[i][j] = 0.f;

    for (int k0 = 0; k0 < K; k0 += 16) {
        // 128 rows x 16 k, 8 bf16 per thread per matrix
        int r = tid >> 1;
        int kk = (tid & 1) << 3;
        {
            const __nv_bfloat16* pa_hi = Ahi + (size_t)(row0 + r) * K + k0 + kk;
            const __nv_bfloat16* pa_lo = Alo + (size_t)(row0 + r) * K + k0 + kk;
            uint4 uh = *(const uint4*)pa_hi;
            uint4 ul = *(const uint4*)pa_lo;
            const __nv_bfloat16* hh = (const __nv_bfloat16*)&uh;
            const __nv_bfloat16* ll = (const __nv_bfloat16*)&ul;
#pragma unroll
            for (int j = 0; j < 8; j++)
                As[kk + j][r] = __bfloat162float(hh[j]) + __bfloat162float(ll[j]);
        }
        {
            const __nv_bfloat16* pb_hi = Bhi + (size_t)(col0 + r) * K + k0 + kk;
            const __nv_bfloat16* pb_lo = Blo + (size_t)(col0 + r) * K + k0 + kk;
            uint4 uh = *(const uint4*)pb_hi;
            uint4 ul = *(const uint4*)pb_lo;
            const __nv_bfloat16* hh = (const __nv_bfloat16*)&uh;
            const __nv_bfloat16* ll = (const __nv_bfloat16*)&ul;
#pragma unroll
            for (int j = 0; j < 8; j++)
                Bs[kk + j][r] = __bfloat162float(hh[j]) + __bfloat162float(ll[j]);
        }
        __syncthreads();
#pragma unroll
        for (int k = 0; k < 16; k++) {
            float a[8], b[8];
#pragma unroll
            for (int q = 0; q < 2; q++) {
                *(float4*)(&a[q * 4]) = *(const float4*)(&As[k][ty * 8 + q * 4]);
                *(float4*)(&b[q * 4]) = *(const float4*)(&Bs[k][tx * 8 + q * 4]);
            }
#pragma unroll
            for (int i = 0; i < 8; i++)
#pragma unroll
                for (int j = 0; j < 8; j++)
                    acc[i][j] = fmaf(a[i], b[j], acc[i][j]);
        }
        __syncthreads();
    }
#pragma unroll
    for (int i = 0; i < 8; i++) {
        int r = row0 + ty * 8 + i;
#pragma unroll
        for (int j = 0; j < 8; j++) {
            int c = col0 + tx * 8 + j;
            float v = acc[i][j];
            if (MODE == 1) v += addsrc[(size_t)r * ldadd + addoff + c];
            if (MODE == 2)
                ((__half*)Cout)[(size_t)r * ldc + c] = __float2half(v);
            else
                ((float*)Cout)[(size_t)r * ldc + c] = v;
        }
    }
#endif
}

// ---------------- fused attention: e -> softmax -> ctx (hi/lo) --------------
__global__ __launch_bounds__(256)
void attn_kernel(const float* __restrict__ b_hid, const float* __restrict__ w_score) {
    __shared__ float hp_s[Hq];
    __shared__ float ws[Hq];
    __shared__ float e_s[Tq];
    const int b = blockIdx.x, tid = threadIdx.x, warp = tid >> 5, lane = tid & 31;

    for (int i = tid; i < Hq; i += 256) {
        hp_s[i] = g_y1[b * NC1 + i] + b_hid[i];   // hp part of merged GEMM1
        ws[i] = w_score[i];
    }
    __syncthreads();

    const __half* fb = g_feat + (size_t)b * Tq * Hq;
    for (int t = warp; t < Tq; t += 8) {
        const __half* fr = fb + (size_t)t * Hq;
        float s = 0.f;
#pragma unroll
        for (int j = 0; j < 2; j++) {
            int h0 = lane * 8 + j * 256;
            uint4 u = *(const uint4*)(fr + h0);
            __half2* hv = (__half2*)&u;
#pragma unroll
            for (int q = 0; q < 4; q++) {
                float2 f = __half22float2(hv[q]);
                int h = h0 + q * 2;
                s += fast_tanh(f.x + hp_s[h]) * ws[h];
                s += fast_tanh(f.y + hp_s[h + 1]) * ws[h + 1];
            }
        }
#pragma unroll
        for (int o = 16; o; o >>= 1) s += __shfl_xor_sync(0xffffffffu, s, o);
        if (lane == 0) e_s[t] = s;
    }
    __syncthreads();

    if (warp == 0) {
        float v0 = e_s[lane], v1 = e_s[lane + 32], v2 = e_s[lane + 64], v3 = e_s[lane + 96];
        float m = fmaxf(fmaxf(v0, v1), fmaxf(v2, v3));
#pragma unroll
        for (int o = 16; o; o >>= 1) m = fmaxf(m, __shfl_xor_sync(0xffffffffu, m, o));
        float x0 = __expf(v0 - m), x1 = __expf(v1 - m), x2 = __expf(v2 - m), x3 = __expf(v3 - m);
        float sum = x0 + x1 + x2 + x3;
#pragma unroll
        for (int o = 16; o; o >>= 1) sum += __shfl_xor_sync(0xffffffffu, sum, o);
        float inv = __fdividef(1.f, sum);
        e_s[lane] = x0 * inv;      e_s[lane + 32] = x1 * inv;
        e_s[lane + 64] = x2 * inv; e_s[lane + 96] = x3 * inv;
    }
    __syncthreads();

    // ctx: 2 columns per thread from fp16 batch_H copy
    const __half* Hb = g_bH16 + (size_t)b * Tq * Iq;
    const int i2 = tid * 2;
    float a0 = 0.f, a1 = 0.f;
#pragma unroll 4
    for (int t = 0; t < Tq; t++) {
        __half2 v = *(const __half2*)(Hb + (size_t)t * Iq + i2);
        float2 f = __half22float2(v);
        float al = e_s[t];
        a0 = fmaf(al, f.x, a0);
        a1 = fmaf(al, f.y, a1);
    }
    split2(a0, &g_ctx_hi[b * Iq + i2], &g_ctx_lo[b * Iq + i2]);
    split2(a1, &g_ctx_hi[b * Iq + i2 + 1], &g_ctx_lo[b * Iq + i2 + 1]);
}

// ---------------- LSTM elementwise ------------------------------------------
__global__ __launch_bounds__(256)
void lstm_kernel(const float* __restrict__ b_ih, const float* __restrict__ b_hh,
                 const float* __restrict__ W_ih, const int* __restrict__ text, int s) {
    int idx = blockIdx.x * blockDim.x + threadIdx.x;  // B*H
    int b = idx >> 9, hh = idx & 511;
    int tc = text[b * Sq + s];
    const float* g = g_gates + (size_t)b * NG;
    const float* wcol = W_ih + Iq + tc;  // one-hot column, row stride I+C

    float gi = g[hh]          + b_ih[hh]          + b_hh[hh]          + wcol[(size_t)(hh)          * (Iq + Cq)];
    float gf = g[Hq + hh]     + b_ih[Hq + hh]     + b_hh[Hq + hh]     + wcol[(size_t)(Hq + hh)     * (Iq + Cq)];
    float gg = g[2 * Hq + hh] + b_ih[2 * Hq + hh] + b_hh[2 * Hq + hh] + wcol[(size_t)(2 * Hq + hh) * (Iq + Cq)];
    float go = g[3 * Hq + hh] + b_ih[3 * Hq + hh] + b_hh[3 * Hq + hh] + wcol[(size_t)(3 * Hq + hh) * (Iq + Cq)];

    float c = g_c[idx];
    float c2 = fast_sigmoid(gf) * c + fast_sigmoid(gi) * fast_tanh(gg);
    float h2 = fast_sigmoid(go) * fast_tanh(c2);
    g_c[idx] = c2;
    g_h[idx] = h2;
    split2(h2, &g_h_hi[idx], &g_h_lo[idx]);
}

// ---------------- generator -------------------------------------------------
__global__ __launch_bounds__(256)
void gen_kernel(const float* __restrict__ W_gen, const float* __restrict__ b_gen,
                float* __restrict__ out, int s) {
    __shared__ float hs[Hq];
    const int b = blockIdx.x, tid = threadIdx.x, warp = tid >> 5, lane = tid & 31;
    for (int i = tid; i < Hq; i += 256) hs[i] = g_h[b * Hq + i];
    __syncthreads();
    for (int c = warp; c < Cq; c += 8) {
        const float* w = W_gen + (size_t)c * Hq;
        float sum = 0.f;
#pragma unroll 4
        for (int h = lane; h < Hq; h += 32) sum = fmaf(hs[h], w[h], sum);
#pragma unroll
        for (int o = 16; o; o >>= 1) sum += __shfl_xor_sync(0xffffffffu, sum, o);
        if (lane == 0) out[((size_t)b * Sq + s) * Cq + c] = sum + b_gen[c];
    }
}

// ---------------- launch ----------------------------------------------------
extern "C" void kernel_launch(void* const* d_in, const int* in_sizes, int n_in,
                              void* d_out, int out_size) {
    const float* batch_H = (const float*)d_in[0];
    const int*   text    = (const int*)d_in[1];
    const float* W_feat  = (const float*)d_in[2];
    const float* W_hid   = (const float*)d_in[3];
    const float* b_hid   = (const float*)d_in[4];
    const float* w_score = (const float*)d_in[5];
    const float* W_ih    = (const float*)d_in[6];
    const float* W_hh    = (const float*)d_in[7];
    const float* b_ih    = (const float*)d_in[8];
    const float* b_hh    = (const float*)d_in[9];
    const float* W_gen   = (const float*)d_in[10];
    const float* b_gen   = (const float*)d_in[11];
    float* out = (float*)d_out;

    __nv_bfloat16 *p_bH_hi, *p_bH_lo, *p_h_hi, *p_h_lo, *p_ctx_hi, *p_ctx_lo;
    __nv_bfloat16 *p_Wc_hi, *p_Wc_lo, *p_Wih_hi, *p_Wih_lo, *p_Wf_hi, *p_Wf_lo;
    float *p_y1, *p_gates;
    __half* p_feat;
    cudaGetSymbolAddress((void**)&p_bH_hi, g_bH_hi);
    cudaGetSymbolAddress((void**)&p_bH_lo, g_bH_lo);
    cudaGetSymbolAddress((void**)&p_h_hi, g_h_hi);
    cudaGetSymbolAddress((void**)&p_h_lo, g_h_lo);
    cudaGetSymbolAddress((void**)&p_ctx_hi, g_ctx_hi);
    cudaGetSymbolAddress((void**)&p_ctx_lo, g_ctx_lo);
    cudaGetSymbolAddress((void**)&p_Wc_hi, g_Wc_hi);
    cudaGetSymbolAddress((void**)&p_Wc_lo, g_Wc_lo);
    cudaGetSymbolAddress((void**)&p_Wih_hi, g_Wih_hi);
    cudaGetSymbolAddress((void**)&p_Wih_lo, g_Wih_lo);
    cudaGetSymbolAddress((void**)&p_Wf_hi, g_Wf_hi);
    cudaGetSymbolAddress((void**)&p_Wf_lo, g_Wf_lo);
    cudaGetSymbolAddress((void**)&p_y1, g_y1);
    cudaGetSymbolAddress((void**)&p_gates, g_gates);
    cudaGetSymbolAddress((void**)&p_feat, g_feat);

    cudaFuncSetAttribute(gemm_tc<0>, cudaFuncAttributeMaxDynamicSharedMemorySize, GEMM_SMEM);
    cudaFuncSetAttribute(gemm_tc<1>, cudaFuncAttributeMaxDynamicSharedMemorySize, GEMM_SMEM);
    cudaFuncSetAttribute(gemm_tc<2>, cudaFuncAttributeMaxDynamicSharedMemorySize, GEMM_SMEM);

    init_kernel<<<(Bq * Hq) / 256, 256>>>();
    prep_bh<<<(Bq * Tq * Iq) / 256, 256>>>(batch_H);
    prep_wc<<<(NC1 * Hq) / 256, 256>>>(W_hid, W_hh);
    prep_wih<<<(NG * Iq) / 256, 256>>>(W_ih);
    prep_wf<<<(Hq * Iq) / 256, 256>>>(W_feat);

    // feat = batch_H @ W_feat^T  [65536 x 512], K = 512, fp16 out
    gemm_tc<2><<<dim3(Hq / 128, (Bq * Tq) / 128), 256, GEMM_SMEM>>>(
        p_bH_hi, p_bH_lo, p_Wf_hi, p_Wf_lo, Iq, p_feat, Hq, nullptr, 0, 0);

    for (int s = 0; s < Sq; s++) {
        // y1 = h @ [W_hid; W_hh]^T  [512 x 2560], K = 512
        gemm_tc<0><<<dim3(NC1 / 128, Bq / 128), 256, GEMM_SMEM>>>(
            p_h_hi, p_h_lo, p_Wc_hi, p_Wc_lo, Hq, p_y1, NC1, nullptr, 0, 0);

        attn_kernel<<<Bq, 256>>>(b_hid, w_score);

        // gates = ctx @ W_ih[:, :I]^T + y1[:, 512:]  [512 x 2048], K = 512
        gemm_tc<1><<<dim3(NG / 128, Bq / 128), 256, GEMM_SMEM>>>(
            p_ctx_hi, p_ctx_lo, p_Wih_hi, p_Wih_lo, Iq, p_gates, NG, p_y1, NC1, Hq);

        lstm_kernel<<<(Bq * Hq) / 256, 256>>>(b_ih, b_hh, W_ih, text, s);
        gen_kernel<<<Bq, 256>>>(W_gen, b_gen, out, s);
    }
}

// round 5
// speedup vs baseline: 2.6527x; 1.3789x over previous
#include <cuda_runtime.h>
#include <cuda_fp16.h>
#include <cuda_bf16.h>
#include <cstdint>

// Problem dims (fixed)
#define Bq 512
#define Tq 128
#define Iq 512
#define Hq 512
#define Cq 97
#define Sq 26
#define NC1 2560   // hp(512) + gates_h(2048)
#define NG  2048   // 4H

#if defined(__CUDA_ARCH_FEAT_SM103_ALL) || defined(__CUDA_ARCH_FEAT_SM100_ALL)
#define HAS_TCGEN05 1
#else
#define HAS_TCGEN05 0
#endif

// ---------------- scratch (static device globals; no allocations) ----------
__device__ __align__(16) __nv_bfloat16 g_bH_hi[(size_t)Bq * Tq * Iq];  // 67MB
__device__ __align__(16) __nv_bfloat16 g_bH_lo[(size_t)Bq * Tq * Iq];  // 67MB
__device__ __align__(16) __half        g_bH16[(size_t)Bq * Tq * Iq];   // 67MB (ctx pass)
__device__ __align__(16) __half        g_feat[(size_t)Bq * Tq * Hq];   // 67MB fp16
__device__ __align__(16) float         g_c[Bq * Hq];
__device__ __align__(16) __nv_bfloat16 g_h_hi[Bq * Hq];
__device__ __align__(16) __nv_bfloat16 g_h_lo[Bq * Hq];
__device__ __align__(16) __nv_bfloat16 g_ctx_hi[Bq * Iq];
__device__ __align__(16) __nv_bfloat16 g_ctx_lo[Bq * Iq];
__device__ __align__(16) float         g_y1[Bq * NC1];                  // [hp | gates_h]
__device__ __align__(16) float         g_gates[Bq * NG];
__device__ __align__(16) __nv_bfloat16 g_Wc_hi[NC1 * Hq];               // [W_hid; W_hh]
__device__ __align__(16) __nv_bfloat16 g_Wc_lo[NC1 * Hq];
__device__ __align__(16) __nv_bfloat16 g_Wih_hi[NG * Iq];               // W_ih[:, :I]
__device__ __align__(16) __nv_bfloat16 g_Wih_lo[NG * Iq];
__device__ __align__(16) __nv_bfloat16 g_Wf_hi[Hq * Iq];
__device__ __align__(16) __nv_bfloat16 g_Wf_lo[Hq * Iq];
__device__ __align__(16) float         g_We[Cq * NG];  // one-hot col of W_ih + b_ih + b_hh

// ---------------- helpers ---------------------------------------------------
__device__ __forceinline__ float fast_sigmoid(float x) {
    return __fdividef(1.f, 1.f + __expf(-x));
}
__device__ __forceinline__ float fast_tanh(float x) {
    float xc = fminf(fmaxf(x, -15.f), 15.f);
    float e = __expf(2.f * xc);
    return __fdividef(e - 1.f, e + 1.f);
}
__device__ __forceinline__ void split2(float a, __nv_bfloat16* hi, __nv_bfloat16* lo) {
    __nv_bfloat16 h = __float2bfloat16(a);
    *hi = h;
    *lo = __float2bfloat16(a - __bfloat162float(h));
}
__device__ __forceinline__ uint32_t s2u(const void* p) {
    uint32_t a;
    asm("{ .reg .u64 t; cvta.to.shared.u64 t, %1; cvt.u32.u64 %0, t; }" : "=r"(a) : "l"(p));
    return a;
}
__device__ __forceinline__ void cpa16(uint32_t s, const void* g) {
    asm volatile("cp.async.cg.shared.global [%0], [%1], 16;" :: "r"(s), "l"(g));
}

#if HAS_TCGEN05
__device__ __forceinline__ uint32_t elect1() {
    uint32_t p;
    asm volatile("{ .reg .pred p; elect.sync _|p, 0xFFFFFFFF; selp.b32 %0, 1, 0, p; }" : "=r"(p));
    return p;
}
__device__ __forceinline__ void mbar_wait(uint32_t a, uint32_t ph) {
    asm volatile(
        "{\n\t.reg .pred P;\n"
        "LW%=:\n\t"
        "mbarrier.try_wait.parity.acquire.cta.shared::cta.b64 P, [%0], %1, 0x989680;\n\t"
        "@!P bra.uni LW%=;\n\t}"
        :: "r"(a), "r"(ph) : "memory");
}
// cg1 SS bf16 MMA, fp32 accum
__device__ __forceinline__ void mma_ss(uint32_t d, uint64_t a, uint64_t b, uint32_t idesc, bool en) {
    uint32_t e = en ? 1u : 0u;
    asm volatile(
        "{\n\t.reg .pred p;\n\t"
        "setp.ne.u32 p, %5, 0;\n\t"
        "tcgen05.mma.cta_group::1.kind::f16 [%0], %1, %2, %3, {%4, %4, %4, %4}, p;\n\t}"
        :: "r"(d), "l"(a), "l"(b), "r"(idesc), "r"(0u), "r"(e) : "memory");
}
__device__ __forceinline__ void ldtm32(uint32_t* r, uint32_t a) {
    asm volatile(
        "tcgen05.ld.sync.aligned.32x32b.x32.b32 "
        "{%0, %1, %2, %3, %4, %5, %6, %7, %8, %9, %10, %11, %12, %13, %14, %15, "
        "%16, %17, %18, %19, %20, %21, %22, %23, %24, %25, %26, %27, %28, %29, %30, %31}, [%32];"
        : "=r"(r[0]), "=r"(r[1]), "=r"(r[2]), "=r"(r[3]), "=r"(r[4]), "=r"(r[5]), "=r"(r[6]), "=r"(r[7]),
          "=r"(r[8]), "=r"(r[9]), "=r"(r[10]), "=r"(r[11]), "=r"(r[12]), "=r"(r[13]), "=r"(r[14]), "=r"(r[15]),
          "=r"(r[16]), "=r"(r[17]), "=r"(r[18]), "=r"(r[19]), "=r"(r[20]), "=r"(r[21]), "=r"(r[22]), "=r"(r[23]),
          "=r"(r[24]), "=r"(r[25]), "=r"(r[26]), "=r"(r[27]), "=r"(r[28]), "=r"(r[29]), "=r"(r[30]), "=r"(r[31])
        : "r"(a));
}
#endif

static constexpr uint64_t DESCBASE =
    (uint64_t(2) << 61) | (uint64_t(1) << 46) | (uint64_t(64) << 32) | (uint64_t(1) << 16); // SW128 K-major
static constexpr uint32_t IDESC_128x128 = 0x8200490u; // F32 acc, bf16 A/B, M=128, N=128
static constexpr int STAGE_SZ = 65536;                 // 4 x 16KB tiles per stage
static constexpr int GEMM_SMEM = 2 * STAGE_SZ + 1024;

// ---------------- prep kernels ----------------------------------------------
__global__ void init_kernel() {
    int i = blockIdx.x * blockDim.x + threadIdx.x;   // B*H
    g_c[i] = 0.f;
    g_h_hi[i] = __float2bfloat16(0.f); g_h_lo[i] = __float2bfloat16(0.f);
}
// 8 elems/thread, vectorized
__global__ void prep_bh(const float* __restrict__ bH) {
    size_t i0 = ((size_t)blockIdx.x * blockDim.x + threadIdx.x) * 8;
    float4 v0 = *(const float4*)(bH + i0);
    float4 v1 = *(const float4*)(bH + i0 + 4);
    float f[8] = {v0.x, v0.y, v0.z, v0.w, v1.x, v1.y, v1.z, v1.w};
    __nv_bfloat16 hi[8], lo[8];
    __half h16[8];
#pragma unroll
    for (int j = 0; j < 8; j++) {
        split2(f[j], &hi[j], &lo[j]);
        h16[j] = __float2half(f[j]);
    }
    *(uint4*)(g_bH_hi + i0) = *(const uint4*)hi;
    *(uint4*)(g_bH_lo + i0) = *(const uint4*)lo;
    *(uint4*)(g_bH16 + i0)  = *(const uint4*)h16;
}
__global__ void prep_wc(const float* __restrict__ W_hid, const float* __restrict__ W_hh) {
    int i = blockIdx.x * blockDim.x + threadIdx.x;  // NC1*512
    int j = i >> 9, k = i & 511;
    float v = (j < Hq) ? W_hid[j * Hq + k] : W_hh[(j - Hq) * Hq + k];
    split2(v, &g_Wc_hi[i], &g_Wc_lo[i]);
}
__global__ void prep_wih(const float* __restrict__ W_ih) {
    int i = blockIdx.x * blockDim.x + threadIdx.x;  // NG*512
    int j = i >> 9, k = i & 511;
    split2(W_ih[j * (Iq + Cq) + k], &g_Wih_hi[i], &g_Wih_lo[i]);
}
__global__ void prep_wf(const float* __restrict__ W_feat) {
    int i = blockIdx.x * blockDim.x + threadIdx.x;  // H*I
    split2(W_feat[i], &g_Wf_hi[i], &g_Wf_lo[i]);
}
// g_We[c][j] = W_ih[j][I+c] + b_ih[j] + b_hh[j]
__global__ void prep_we(const float* __restrict__ W_ih, const float* __restrict__ b_ih,
                        const float* __restrict__ b_hh) {
    int i = blockIdx.x * blockDim.x + threadIdx.x;  // Cq*NG
    if (i >= Cq * NG) return;
    int c = i / NG, j = i - c * NG;
    g_We[i] = W_ih[(size_t)j * (Iq + Cq) + Iq + c] + b_ih[j] + b_hh[j];
}

// ---------------- split-bf16 GEMM: C[M,N] = A[M,K] @ B[N,K]^T ---------------
// MODE 0: fp32 out.  MODE 1: fp32 out + addsrc[r*ldadd + addoff + col].  MODE 2: fp16 out.
// sm_103a: tcgen05 with 2-stage cp.async pipeline.  Plain sm_103: SIMT fallback.
template <int MODE>
__global__ __launch_bounds__(256)
void gemm_tc(const __nv_bfloat16* __restrict__ Ahi, const __nv_bfloat16* __restrict__ Alo,
             const __nv_bfloat16* __restrict__ Bhi, const __nv_bfloat16* __restrict__ Blo,
             int K, void* Cout, int ldc,
             const float* __restrict__ addsrc, int ldadd, int addoff) {
#if HAS_TCGEN05
    extern __shared__ char dsm[];
    __shared__ uint32_t s_tmem[2];
    __shared__ __align__(8) uint64_t s_mbar;
    const int tid = threadIdx.x, wid = tid >> 5, lane = tid & 31;
    const int row0 = blockIdx.y * 128, col0 = blockIdx.x * 128;

    uint32_t ctrl = s2u(s_tmem);
    uint32_t mbar = s2u(&s_mbar);
    if (wid == 0)
        asm volatile("tcgen05.alloc.cta_group::1.sync.aligned.shared::cta.b32 [%0], %1;"
                     :: "r"(ctrl), "r"(128) : "memory");
    if (tid == 0)
        asm volatile("mbarrier.init.shared.b64 [%0], %1;" :: "r"(mbar), "r"(1) : "memory");
    __syncthreads();
    const uint32_t tmem = s_tmem[0];

    const uint32_t tile = (s2u(dsm) + 1023u) & ~1023u;

    // per-thread swizzled smem offsets (4 x 16B pieces covering 128x64 bf16 tile)
    uint32_t soff[4];
    size_t goff[4];
#pragma unroll
    for (int s4 = 0; s4 < 4; s4++) {
        int v = tid + (s4 << 8);
        int r = v >> 3;
        int c8 = (v & 7) << 3;
        uint32_t so = (uint32_t)(r * 128 + c8 * 2);
        so ^= (so >> 3) & 0x70;
        soff[s4] = so;
        goff[s4] = (size_t)r * K + c8;   // add row0/col0*K and chunk*64 at use
    }
    const size_t aBase = (size_t)row0 * K;
    const size_t bBase = (size_t)col0 * K;

    const int nchunk = K >> 6;

    auto load_chunk = [&](int c, int st) {
        uint32_t base = tile + st * STAGE_SZ;
        size_t kofs = (size_t)c * 64;
#pragma unroll
        for (int s4 = 0; s4 < 4; s4++) {
            size_t ga = aBase + goff[s4] + kofs;
            size_t gb = bBase + goff[s4] + kofs;
            uint32_t so = soff[s4];
            cpa16(base + so,         Ahi + ga);
            cpa16(base + 16384 + so, Alo + ga);
            cpa16(base + 32768 + so, Bhi + gb);
            cpa16(base + 49152 + so, Blo + gb);
        }
        asm volatile("cp.async.commit_group;" ::: "memory");
    };

    load_chunk(0, 0);

    for (int c = 0; c < nchunk; c++) {
        const int st = c & 1;
        // buffer (c+1)&1 was read by MMA of chunk c-1 -> wait its commit
        if (c >= 1) mbar_wait(mbar, (uint32_t)((c - 1) & 1));
        if (c + 1 < nchunk) {
            load_chunk(c + 1, (c + 1) & 1);
            asm volatile("cp.async.wait_group 1;" ::: "memory");
        } else {
            asm volatile("cp.async.wait_group 0;" ::: "memory");
        }
        asm volatile("fence.proxy.async.shared::cta;" ::: "memory");
        __syncthreads();

        if (wid == 0 && elect1()) {
            uint32_t base = tile + st * STAGE_SZ;
            const uint64_t dA0 = DESCBASE | ((base >> 4) & 0x3FFF);
            const uint64_t dA1 = DESCBASE | (((base + 16384) >> 4) & 0x3FFF);
            const uint64_t dB0 = DESCBASE | (((base + 32768) >> 4) & 0x3FFF);
            const uint64_t dB1 = DESCBASE | (((base + 49152) >> 4) & 0x3FFF);
#pragma unroll
            for (int ks = 0; ks < 4; ks++)
                mma_ss(tmem, dA0 + ks * 2, dB0 + ks * 2, IDESC_128x128, !(c == 0 && ks == 0));
#pragma unroll
            for (int ks = 0; ks < 4; ks++)
                mma_ss(tmem, dA0 + ks * 2, dB1 + ks * 2, IDESC_128x128, true);
#pragma unroll
            for (int ks = 0; ks < 4; ks++)
                mma_ss(tmem, dA1 + ks * 2, dB0 + ks * 2, IDESC_128x128, true);
            asm volatile(
                "tcgen05.commit.cta_group::1.mbarrier::arrive::one.shared::cluster.b64 [%0];"
                :: "r"(mbar) : "memory");
        }
    }
    mbar_wait(mbar, (uint32_t)((nchunk - 1) & 1));
    asm volatile("tcgen05.fence::after_thread_sync;" ::: "memory");

    // epilogue: 8 warps, warp w -> subpartition (w&3) rows, col-half (w>>2)
    uint32_t regs[64];
    const int ch = wid >> 2, sp = wid & 3;
    ldtm32(regs, tmem + ch * 64);
    ldtm32(regs + 32, tmem + ch * 64 + 32);
    asm volatile("tcgen05.wait::ld.sync.aligned;" ::: "memory");
    asm volatile("tcgen05.fence::before_thread_sync;" ::: "memory");
    const int r = row0 + sp * 32 + lane;
    const int cb = col0 + ch * 64;
    if (MODE == 2) {
        __half* C = (__half*)Cout;
#pragma unroll
        for (int j = 0; j < 64; j += 2) {
            __half2 h2 = __floats2half2_rn(__uint_as_float(regs[j]), __uint_as_float(regs[j + 1]));
            *(__half2*)(C + (size_t)r * ldc + cb + j) = h2;
        }
    } else {
        float* C = (float*)Cout;
#pragma unroll
        for (int j = 0; j < 64; j += 4) {
            float4 v;
            v.x = __uint_as_float(regs[j]);
            v.y = __uint_as_float(regs[j + 1]);
            v.z = __uint_as_float(regs[j + 2]);
            v.w = __uint_as_float(regs[j + 3]);
            if (MODE == 1) {
                const float* ap = addsrc + (size_t)r * ldadd + addoff + cb + j;
                v.x += ap[0]; v.y += ap[1]; v.z += ap[2]; v.w += ap[3];
            }
            *(float4*)(C + (size_t)r * ldc + cb + j) = v;
        }
    }
    __syncthreads();
    if (wid == 0) {
        if (lane == 0)
            asm volatile("mbarrier.inval.shared.b64 [%0];" :: "r"(mbar) : "memory");
        asm volatile("tcgen05.relinquish_alloc_permit.cta_group::1.sync.aligned;");
        asm volatile("tcgen05.dealloc.cta_group::1.sync.aligned.b32 %0, %1;" :: "r"(tmem), "r"(128));
    }
#else
    // -------- SIMT fallback (plain sm_103 compilation unit): correct path ----
    __shared__ float As[16][128];
    __shared__ float Bs[16][128];
    const int tid = threadIdx.x;
    const int tx = tid & 15, ty = tid >> 4;
    const int row0 = blockIdx.y * 128, col0 = blockIdx.x * 128;

    float acc[8][8];
#pragma unroll
    for (int i = 0; i < 8; i++)
#pragma unroll
        for (int j = 0; j < 8; j++) acc[i][j] = 0.f;

    for (int k0 = 0; k0 < K; k0 += 16) {
        int r = tid >> 1;
        int kk = (tid & 1) << 3;
        {
            uint4 uh = *(const uint4*)(Ahi + (size_t)(row0 + r) * K + k0 + kk);
            uint4 ul = *(const uint4*)(Alo + (size_t)(row0 + r) * K + k0 + kk);
            const __nv_bfloat16* hh = (const __nv_bfloat16*)&uh;
            const __nv_bfloat16* ll = (const __nv_bfloat16*)&ul;
#pragma unroll
            for (int j = 0; j < 8; j++)
                As[kk + j][r] = __bfloat162float(hh[j]) + __bfloat162float(ll[j]);
        }
        {
            uint4 uh = *(const uint4*)(Bhi + (size_t)(col0 + r) * K + k0 + kk);
            uint4 ul = *(const uint4*)(Blo + (size_t)(col0 + r) * K + k0 + kk);
            const __nv_bfloat16* hh = (const __nv_bfloat16*)&uh;
            const __nv_bfloat16* ll = (const __nv_bfloat16*)&ul;
#pragma unroll
            for (int j = 0; j < 8; j++)
                Bs[kk + j][r] = __bfloat162float(hh[j]) + __bfloat162float(ll[j]);
        }
        __syncthreads();
#pragma unroll
        for (int k = 0; k < 16; k++) {
            float a[8], b[8];
#pragma unroll
            for (int q = 0; q < 2; q++) {
                *(float4*)(&a[q * 4]) = *(const float4*)(&As[k][ty * 8 + q * 4]);
                *(float4*)(&b[q * 4]) = *(const float4*)(&Bs[k][tx * 8 + q * 4]);
            }
#pragma unroll
            for (int i = 0; i < 8; i++)
#pragma unroll
                for (int j = 0; j < 8; j++)
                    acc[i][j] = fmaf(a[i], b[j], acc[i][j]);
        }
        __syncthreads();
    }
#pragma unroll
    for (int i = 0; i < 8; i++) {
        int r = row0 + ty * 8 + i;
#pragma unroll
        for (int j = 0; j < 8; j++) {
            int c = col0 + tx * 8 + j;
            float v = acc[i][j];
            if (MODE == 1) v += addsrc[(size_t)r * ldadd + addoff + c];
            if (MODE == 2)
                ((__half*)Cout)[(size_t)r * ldc + c] = __float2half(v);
            else
                ((float*)Cout)[(size_t)r * ldc + c] = v;
        }
    }
#endif
}

// ---------------- fused attention: e -> softmax -> ctx (hi/lo) --------------
__global__ __launch_bounds__(256)
void attn_kernel(const float* __restrict__ b_hid, const float* __restrict__ w_score) {
    __shared__ float hp_s[Hq];
    __shared__ float ws[Hq];
    __shared__ float e_s[Tq];
    const int b = blockIdx.x, tid = threadIdx.x, warp = tid >> 5, lane = tid & 31;

    for (int i = tid; i < Hq; i += 256) {
        hp_s[i] = g_y1[b * NC1 + i] + b_hid[i];   // hp part of merged GEMM1
        ws[i] = w_score[i];
    }
    __syncthreads();

    const __half* fb = g_feat + (size_t)b * Tq * Hq;
    for (int t = warp; t < Tq; t += 8) {
        const __half* fr = fb + (size_t)t * Hq;
        float s = 0.f;
#pragma unroll
        for (int j = 0; j < 2; j++) {
            int h0 = lane * 8 + j * 256;
            uint4 u = *(const uint4*)(fr + h0);
            __half2* hv = (__half2*)&u;
#pragma unroll
            for (int q = 0; q < 4; q++) {
                float2 f = __half22float2(hv[q]);
                int h = h0 + q * 2;
                s += fast_tanh(f.x + hp_s[h]) * ws[h];
                s += fast_tanh(f.y + hp_s[h + 1]) * ws[h + 1];
            }
        }
#pragma unroll
        for (int o = 16; o; o >>= 1) s += __shfl_xor_sync(0xffffffffu, s, o);
        if (lane == 0) e_s[t] = s;
    }
    __syncthreads();

    if (warp == 0) {
        float v0 = e_s[lane], v1 = e_s[lane + 32], v2 = e_s[lane + 64], v3 = e_s[lane + 96];
        float m = fmaxf(fmaxf(v0, v1), fmaxf(v2, v3));
#pragma unroll
        for (int o = 16; o; o >>= 1) m = fmaxf(m, __shfl_xor_sync(0xffffffffu, m, o));
        float x0 = __expf(v0 - m), x1 = __expf(v1 - m), x2 = __expf(v2 - m), x3 = __expf(v3 - m);
        float sum = x0 + x1 + x2 + x3;
#pragma unroll
        for (int o = 16; o; o >>= 1) sum += __shfl_xor_sync(0xffffffffu, sum, o);
        float inv = __fdividef(1.f, sum);
        e_s[lane] = x0 * inv;      e_s[lane + 32] = x1 * inv;
        e_s[lane + 64] = x2 * inv; e_s[lane + 96] = x3 * inv;
    }
    __syncthreads();

    // ctx: 2 columns per thread from fp16 batch_H copy
    const __half* Hb = g_bH16 + (size_t)b * Tq * Iq;
    const int i2 = tid * 2;
    float a0 = 0.f, a1 = 0.f;
#pragma unroll 4
    for (int t = 0; t < Tq; t++) {
        __half2 v = *(const __half2*)(Hb + (size_t)t * Iq + i2);
        float2 f = __half22float2(v);
        float al = e_s[t];
        a0 = fmaf(al, f.x, a0);
        a1 = fmaf(al, f.y, a1);
    }
    split2(a0, &g_ctx_hi[b * Iq + i2], &g_ctx_lo[b * Iq + i2]);
    split2(a1, &g_ctx_hi[b * Iq + i2 + 1], &g_ctx_lo[b * Iq + i2 + 1]);
}

// ---------------- fused LSTM pointwise + generator (one block per b) ---------
__global__ __launch_bounds__(512)
void lstm_gen_kernel(const int* __restrict__ text,
                     const float* __restrict__ W_gen, const float* __restrict__ b_gen,
                     float* __restrict__ out, int s) {
    __shared__ float hs[Hq];
    const int b = blockIdx.x, tid = threadIdx.x;
    const int tc = text[b * Sq + s];

    // LSTM: thread tid = hidden unit hh
    {
        const int hh = tid;
        const float* g = g_gates + (size_t)b * NG;
        const float* we = g_We + (size_t)tc * NG;
        float gi = g[hh]          + we[hh];
        float gf = g[Hq + hh]     + we[Hq + hh];
        float gg = g[2 * Hq + hh] + we[2 * Hq + hh];
        float go = g[3 * Hq + hh] + we[3 * Hq + hh];

        const int idx = b * Hq + hh;
        float c = g_c[idx];
        float c2 = fast_sigmoid(gf) * c + fast_sigmoid(gi) * fast_tanh(gg);
        float h2 = fast_sigmoid(go) * fast_tanh(c2);
        g_c[idx] = c2;
        split2(h2, &g_h_hi[idx], &g_h_lo[idx]);
        hs[hh] = h2;
    }
    __syncthreads();

    // generator: 16 warps cover 97 classes
    const int warp = tid >> 5, lane = tid & 31;
    for (int c = warp; c < Cq; c += 16) {
        const float* w = W_gen + (size_t)c * Hq;
        float sum = 0.f;
#pragma unroll 4
        for (int h = lane; h < Hq; h += 32) sum = fmaf(hs[h], w[h], sum);
#pragma unroll
        for (int o = 16; o; o >>= 1) sum += __shfl_xor_sync(0xffffffffu, sum, o);
        if (lane == 0) out[((size_t)b * Sq + s) * Cq + c] = sum + b_gen[c];
    }
}

// ---------------- launch ----------------------------------------------------
extern "C" void kernel_launch(void* const* d_in, const int* in_sizes, int n_in,
                              void* d_out, int out_size) {
    const float* batch_H = (const float*)d_in[0];
    const int*   text    = (const int*)d_in[1];
    const float* W_feat  = (const float*)d_in[2];
    const float* W_hid   = (const float*)d_in[3];
    const float* b_hid   = (const float*)d_in[4];
    const float* w_score = (const float*)d_in[5];
    const float* W_ih    = (const float*)d_in[6];
    const float* W_hh    = (const float*)d_in[7];
    const float* b_ih    = (const float*)d_in[8];
    const float* b_hh    = (const float*)d_in[9];
    const float* W_gen   = (const float*)d_in[10];
    const float* b_gen   = (const float*)d_in[11];
    float* out = (float*)d_out;

    __nv_bfloat16 *p_bH_hi, *p_bH_lo, *p_h_hi, *p_h_lo, *p_ctx_hi, *p_ctx_lo;
    __nv_bfloat16 *p_Wc_hi, *p_Wc_lo, *p_Wih_hi, *p_Wih_lo, *p_Wf_hi, *p_Wf_lo;
    float *p_y1, *p_gates;
    __half* p_feat;
    cudaGetSymbolAddress((void**)&p_bH_hi, g_bH_hi);
    cudaGetSymbolAddress((void**)&p_bH_lo, g_bH_lo);
    cudaGetSymbolAddress((void**)&p_h_hi, g_h_hi);
    cudaGetSymbolAddress((void**)&p_h_lo, g_h_lo);
    cudaGetSymbolAddress((void**)&p_ctx_hi, g_ctx_hi);
    cudaGetSymbolAddress((void**)&p_ctx_lo, g_ctx_lo);
    cudaGetSymbolAddress((void**)&p_Wc_hi, g_Wc_hi);
    cudaGetSymbolAddress((void**)&p_Wc_lo, g_Wc_lo);
    cudaGetSymbolAddress((void**)&p_Wih_hi, g_Wih_hi);
    cudaGetSymbolAddress((void**)&p_Wih_lo, g_Wih_lo);
    cudaGetSymbolAddress((void**)&p_Wf_hi, g_Wf_hi);
    cudaGetSymbolAddress((void**)&p_Wf_lo, g_Wf_lo);
    cudaGetSymbolAddress((void**)&p_y1, g_y1);
    cudaGetSymbolAddress((void**)&p_gates, g_gates);
    cudaGetSymbolAddress((void**)&p_feat, g_feat);

    cudaFuncSetAttribute(gemm_tc<0>, cudaFuncAttributeMaxDynamicSharedMemorySize, GEMM_SMEM);
    cudaFuncSetAttribute(gemm_tc<1>, cudaFuncAttributeMaxDynamicSharedMemorySize, GEMM_SMEM);
    cudaFuncSetAttribute(gemm_tc<2>, cudaFuncAttributeMaxDynamicSharedMemorySize, GEMM_SMEM);

    init_kernel<<<(Bq * Hq) / 256, 256>>>();
    prep_bh<<<((size_t)Bq * Tq * Iq) / (256 * 8), 256>>>(batch_H);
    prep_wc<<<(NC1 * Hq) / 256, 256>>>(W_hid, W_hh);
    prep_wih<<<(NG * Iq) / 256, 256>>>(W_ih);
    prep_wf<<<(Hq * Iq) / 256, 256>>>(W_feat);
    prep_we<<<(Cq * NG + 255) / 256, 256>>>(W_ih, b_ih, b_hh);

    // feat = batch_H @ W_feat^T  [65536 x 512], K = 512, fp16 out
    gemm_tc<2><<<dim3(Hq / 128, (Bq * Tq) / 128), 256, GEMM_SMEM>>>(
        p_bH_hi, p_bH_lo, p_Wf_hi, p_Wf_lo, Iq, p_feat, Hq, nullptr, 0, 0);

    for (int s = 0; s < Sq; s++) {
        // y1 = h @ [W_hid; W_hh]^T  [512 x 2560], K = 512
        gemm_tc<0><<<dim3(NC1 / 128, Bq / 128), 256, GEMM_SMEM>>>(
            p_h_hi, p_h_lo, p_Wc_hi, p_Wc_lo, Hq, p_y1, NC1, nullptr, 0, 0);

        attn_kernel<<<Bq, 256>>>(b_hid, w_score);

        // gates = ctx @ W_ih[:, :I]^T + y1[:, 512:]  [512 x 2048], K = 512
        gemm_tc<1><<<dim3(NG / 128, Bq / 128), 256, GEMM_SMEM>>>(
            p_ctx_hi, p_ctx_lo, p_Wih_hi, p_Wih_lo, Iq, p_gates, NG, p_y1, NC1, Hq);

        // fused LSTM pointwise + generator
        lstm_gen_kernel<<<Bq, 512>>>(text, W_gen, b_gen, out, s);
    }
}

// round 6
// speedup vs baseline: 2.7927x; 1.0528x over previous
#include <cuda_runtime.h>
#include <cuda_fp16.h>
#include <cuda_bf16.h>
#include <cstdint>

// Problem dims (fixed)
#define Bq 512
#define Tq 128
#define Iq 512
#define Hq 512
#define Cq 97
#define Sq 26
#define NC1 2560   // hp(512) + interleaved gates_h(2048)
#define NG  2048   // 4H interleaved: col 4*j+g = gate g of unit j

#if defined(__CUDA_ARCH_FEAT_SM103_ALL) || defined(__CUDA_ARCH_FEAT_SM100_ALL)
#define HAS_TCGEN05 1
#else
#define HAS_TCGEN05 0
#endif

// ---------------- scratch (static device globals; no allocations) ----------
__device__ __align__(16) __nv_bfloat16 g_bH_hi[(size_t)Bq * Tq * Iq];
__device__ __align__(16) __nv_bfloat16 g_bH_lo[(size_t)Bq * Tq * Iq];
__device__ __align__(16) __half        g_bH16[(size_t)Bq * Tq * Iq];
__device__ __align__(16) __half        g_feat[(size_t)Bq * Tq * Hq];
__device__ __align__(16) float         g_h[Bq * Hq];
__device__ __align__(16) float         g_c[Bq * Hq];
__device__ __align__(16) __nv_bfloat16 g_h_hi[Bq * Hq];
__device__ __align__(16) __nv_bfloat16 g_h_lo[Bq * Hq];
__device__ __align__(16) __nv_bfloat16 g_ctx_hi[Bq * Iq];
__device__ __align__(16) __nv_bfloat16 g_ctx_lo[Bq * Iq];
__device__ __align__(16) float         g_y1[Bq * NC1];
__device__ __align__(16) __nv_bfloat16 g_Wc_hi[NC1 * Hq];
__device__ __align__(16) __nv_bfloat16 g_Wc_lo[NC1 * Hq];
__device__ __align__(16) __nv_bfloat16 g_Wih_hi[NG * Iq];
__device__ __align__(16) __nv_bfloat16 g_Wih_lo[NG * Iq];
__device__ __align__(16) __nv_bfloat16 g_Wf_hi[Hq * Iq];
__device__ __align__(16) __nv_bfloat16 g_Wf_lo[Hq * Iq];
__device__ __align__(16) float         g_We[Cq * NG];  // interleaved one-hot col + biases

// ---------------- helpers ---------------------------------------------------
__device__ __forceinline__ float fast_sigmoid(float x) {
    return __fdividef(1.f, 1.f + __expf(-x));
}
__device__ __forceinline__ float fast_tanh(float x) {
    float xc = fminf(fmaxf(x, -15.f), 15.f);
    float e = __expf(2.f * xc);
    return __fdividef(e - 1.f, e + 1.f);
}
__device__ __forceinline__ float tanh_approx(float x) {
    float y;
    asm("tanh.approx.f32 %0, %1;" : "=f"(y) : "f"(x));
    return y;
}
__device__ __forceinline__ void split2(float a, __nv_bfloat16* hi, __nv_bfloat16* lo) {
    __nv_bfloat16 h = __float2bfloat16(a);
    *hi = h;
    *lo = __float2bfloat16(a - __bfloat162float(h));
}
__device__ __forceinline__ uint32_t s2u(const void* p) {
    uint32_t a;
    asm("{ .reg .u64 t; cvta.to.shared.u64 t, %1; cvt.u32.u64 %0, t; }" : "=r"(a) : "l"(p));
    return a;
}
__device__ __forceinline__ void cpa16(uint32_t s, const void* g) {
    asm volatile("cp.async.cg.shared.global [%0], [%1], 16;" :: "r"(s), "l"(g));
}

#if HAS_TCGEN05
__device__ __forceinline__ uint32_t elect1() {
    uint32_t p;
    asm volatile("{ .reg .pred p; elect.sync _|p, 0xFFFFFFFF; selp.b32 %0, 1, 0, p; }" : "=r"(p));
    return p;
}
__device__ __forceinline__ void mbar_wait(uint32_t a, uint32_t ph) {
    asm volatile(
        "{\n\t.reg .pred P;\n"
        "LW%=:\n\t"
        "mbarrier.try_wait.parity.acquire.cta.shared::cta.b64 P, [%0], %1, 0x989680;\n\t"
        "@!P bra.uni LW%=;\n\t}"
        :: "r"(a), "r"(ph) : "memory");
}
__device__ __forceinline__ void mma_ss(uint32_t d, uint64_t a, uint64_t b, uint32_t idesc, bool en) {
    uint32_t e = en ? 1u : 0u;
    asm volatile(
        "{\n\t.reg .pred p;\n\t"
        "setp.ne.u32 p, %5, 0;\n\t"
        "tcgen05.mma.cta_group::1.kind::f16 [%0], %1, %2, %3, {%4, %4, %4, %4}, p;\n\t}"
        :: "r"(d), "l"(a), "l"(b), "r"(idesc), "r"(0u), "r"(e) : "memory");
}
__device__ __forceinline__ void ldtm32(uint32_t* r, uint32_t a) {
    asm volatile(
        "tcgen05.ld.sync.aligned.32x32b.x32.b32 "
        "{%0, %1, %2, %3, %4, %5, %6, %7, %8, %9, %10, %11, %12, %13, %14, %15, "
        "%16, %17, %18, %19, %20, %21, %22, %23, %24, %25, %26, %27, %28, %29, %30, %31}, [%32];"
        : "=r"(r[0]), "=r"(r[1]), "=r"(r[2]), "=r"(r[3]), "=r"(r[4]), "=r"(r[5]), "=r"(r[6]), "=r"(r[7]),
          "=r"(r[8]), "=r"(r[9]), "=r"(r[10]), "=r"(r[11]), "=r"(r[12]), "=r"(r[13]), "=r"(r[14]), "=r"(r[15]),
          "=r"(r[16]), "=r"(r[17]), "=r"(r[18]), "=r"(r[19]), "=r"(r[20]), "=r"(r[21]), "=r"(r[22]), "=r"(r[23]),
          "=r"(r[24]), "=r"(r[25]), "=r"(r[26]), "=r"(r[27]), "=r"(r[28]), "=r"(r[29]), "=r"(r[30]), "=r"(r[31])
        : "r"(a));
}
#endif

static constexpr uint64_t DESCBASE =
    (uint64_t(2) << 61) | (uint64_t(1) << 46) | (uint64_t(64) << 32) | (uint64_t(1) << 16); // SW128 K-major
static constexpr uint32_t IDESC_128x128 = 0x8200490u; // F32 acc, bf16 A/B, M=128, N=128
static constexpr int STAGE_SZ = 65536;                 // 4 x 16KB tiles per stage
static constexpr int GEMM_SMEM = 3 * STAGE_SZ + 1024;  // 3-stage pipeline

// ---------------- prep kernels ----------------------------------------------
// 8 elems/thread, vectorized
__global__ void prep_bh(const float* __restrict__ bH) {
    size_t i0 = ((size_t)blockIdx.x * blockDim.x + threadIdx.x) * 8;
    float4 v0 = *(const float4*)(bH + i0);
    float4 v1 = *(const float4*)(bH + i0 + 4);
    float f[8] = {v0.x, v0.y, v0.z, v0.w, v1.x, v1.y, v1.z, v1.w};
    __nv_bfloat16 hi[8], lo[8];
    __half h16[8];
#pragma unroll
    for (int j = 0; j < 8; j++) {
        split2(f[j], &hi[j], &lo[j]);
        h16[j] = __float2half(f[j]);
    }
    *(uint4*)(g_bH_hi + i0) = *(const uint4*)hi;
    *(uint4*)(g_bH_lo + i0) = *(const uint4*)lo;
    *(uint4*)(g_bH16 + i0)  = *(const uint4*)h16;
}
// all weight prep + state init in one kernel (gate-interleaved layouts)
__global__ void prep_w(const float* __restrict__ W_hid, const float* __restrict__ W_hh,
                       const float* __restrict__ W_ih, const float* __restrict__ W_feat,
                       const float* __restrict__ b_ih, const float* __restrict__ b_hh) {
    int idx = blockIdx.x * blockDim.x + threadIdx.x;
    if (idx < NC1 * Hq) {                          // Wc = [W_hid ; interleaved W_hh]
        int j = idx >> 9, k = idx & 511;
        float v;
        if (j < Hq) v = W_hid[j * Hq + k];
        else {
            int jj = j - Hq, j2 = jj >> 2, gg = jj & 3;
            v = W_hh[(size_t)(gg * Hq + j2) * Hq + k];
        }
        split2(v, &g_Wc_hi[idx], &g_Wc_lo[idx]);
        return;
    }
    idx -= NC1 * Hq;
    if (idx < NG * Iq) {                           // interleaved W_ih[:, :I]
        int j = idx >> 9, k = idx & 511;
        int j2 = j >> 2, gg = j & 3;
        split2(W_ih[(size_t)(gg * Hq + j2) * (Iq + Cq) + k], &g_Wih_hi[idx], &g_Wih_lo[idx]);
        return;
    }
    idx -= NG * Iq;
    if (idx < Hq * Iq) {                           // W_feat
        split2(W_feat[idx], &g_Wf_hi[idx], &g_Wf_lo[idx]);
        return;
    }
    idx -= Hq * Iq;
    if (idx < Cq * NG) {                           // We[c][j] interleaved + biases
        int c = idx / NG, j = idx - c * NG;
        int j2 = j >> 2, gg = j & 3;
        int rr = gg * Hq + j2;
        g_We[idx] = W_ih[(size_t)rr * (Iq + Cq) + Iq + c] + b_ih[rr] + b_hh[rr];
        return;
    }
    idx -= Cq * NG;
    if (idx < Bq * Hq) {                           // init state
        g_c[idx] = 0.f;
        g_h_hi[idx] = __float2bfloat16(0.f);
        g_h_lo[idx] = __float2bfloat16(0.f);
    }
}
static constexpr int PREPW_ITEMS = NC1 * Hq + NG * Iq + Hq * Iq + Cq * NG + Bq * Hq;

// ---------------- split-bf16 GEMM: C[M,N] = A[M,K] @ B[N,K]^T ---------------
// MODE 0: fp32 out. MODE 2: fp16 out. MODE 3: fused LSTM epilogue (gate-interleaved).
template <int MODE>
__global__ __launch_bounds__(256)
void gemm_tc(const __nv_bfloat16* __restrict__ Ahi, const __nv_bfloat16* __restrict__ Alo,
             const __nv_bfloat16* __restrict__ Bhi, const __nv_bfloat16* __restrict__ Blo,
             int K, void* Cout, int ldc,
             const float* __restrict__ addsrc, int ldadd, int addoff,
             const int* __restrict__ text, int step) {
#if HAS_TCGEN05
    extern __shared__ char dsm[];
    __shared__ uint32_t s_tmem[2];
    __shared__ __align__(8) uint64_t s_mbar;
    const int tid = threadIdx.x, wid = tid >> 5, lane = tid & 31;
    const int row0 = blockIdx.y * 128, col0 = blockIdx.x * 128;

    uint32_t ctrl = s2u(s_tmem);
    uint32_t mbar = s2u(&s_mbar);
    if (wid == 0)
        asm volatile("tcgen05.alloc.cta_group::1.sync.aligned.shared::cta.b32 [%0], %1;"
                     :: "r"(ctrl), "r"(128) : "memory");
    if (tid == 0)
        asm volatile("mbarrier.init.shared.b64 [%0], %1;" :: "r"(mbar), "r"(1) : "memory");
    __syncthreads();
    const uint32_t tmem = s_tmem[0];

    const uint32_t tile = (s2u(dsm) + 1023u) & ~1023u;

    uint32_t soff[4];
    size_t goff[4];
#pragma unroll
    for (int s4 = 0; s4 < 4; s4++) {
        int v = tid + (s4 << 8);
        int r = v >> 3;
        int c8 = (v & 7) << 3;
        uint32_t so = (uint32_t)(r * 128 + c8 * 2);
        so ^= (so >> 3) & 0x70;
        soff[s4] = so;
        goff[s4] = (size_t)r * K + c8;
    }
    const size_t aBase = (size_t)row0 * K;
    const size_t bBase = (size_t)col0 * K;
    const int nchunk = K >> 6;

    auto load_chunk = [&](int c, int st) {
        uint32_t base = tile + st * STAGE_SZ;
        size_t kofs = (size_t)c * 64;
#pragma unroll
        for (int s4 = 0; s4 < 4; s4++) {
            size_t ga = aBase + goff[s4] + kofs;
            size_t gb = bBase + goff[s4] + kofs;
            uint32_t so = soff[s4];
            cpa16(base + so,         Ahi + ga);
            cpa16(base + 16384 + so, Alo + ga);
            cpa16(base + 32768 + so, Bhi + gb);
            cpa16(base + 49152 + so, Blo + gb);
        }
        asm volatile("cp.async.commit_group;" ::: "memory");
    };

    load_chunk(0, 0);
    if (nchunk > 1) load_chunk(1, 1);

    int st = 0;
    for (int c = 0; c < nchunk; c++) {
        if (c + 2 < nchunk) {
            // buf (c+2)%3 held chunk c-1 -> wait its MMA commit before overwrite
            if (c >= 1) mbar_wait(mbar, (uint32_t)((c - 1) & 1));
            load_chunk(c + 2, (st + 2 >= 3) ? st - 1 : st + 2);
            asm volatile("cp.async.wait_group 2;" ::: "memory");
        } else if (c + 1 < nchunk) {
            if (c >= 1) mbar_wait(mbar, (uint32_t)((c - 1) & 1));
            asm volatile("cp.async.wait_group 1;" ::: "memory");
        } else {
            if (c >= 1) mbar_wait(mbar, (uint32_t)((c - 1) & 1));
            asm volatile("cp.async.wait_group 0;" ::: "memory");
        }
        asm volatile("fence.proxy.async.shared::cta;" ::: "memory");
        __syncthreads();

        if (wid == 0 && elect1()) {
            uint32_t base = tile + st * STAGE_SZ;
            const uint64_t dA0 = DESCBASE | ((base >> 4) & 0x3FFF);
            const uint64_t dA1 = DESCBASE | (((base + 16384) >> 4) & 0x3FFF);
            const uint64_t dB0 = DESCBASE | (((base + 32768) >> 4) & 0x3FFF);
            const uint64_t dB1 = DESCBASE | (((base + 49152) >> 4) & 0x3FFF);
#pragma unroll
            for (int ks = 0; ks < 4; ks++)
                mma_ss(tmem, dA0 + ks * 2, dB0 + ks * 2, IDESC_128x128, !(c == 0 && ks == 0));
#pragma unroll
            for (int ks = 0; ks < 4; ks++)
                mma_ss(tmem, dA0 + ks * 2, dB1 + ks * 2, IDESC_128x128, true);
#pragma unroll
            for (int ks = 0; ks < 4; ks++)
                mma_ss(tmem, dA1 + ks * 2, dB0 + ks * 2, IDESC_128x128, true);
            asm volatile(
                "tcgen05.commit.cta_group::1.mbarrier::arrive::one.shared::cluster.b64 [%0];"
                :: "r"(mbar) : "memory");
        }
        st = (st + 1 >= 3) ? 0 : st + 1;
    }
    mbar_wait(mbar, (uint32_t)((nchunk - 1) & 1));
    asm volatile("tcgen05.fence::after_thread_sync;" ::: "memory");

    // epilogue: 8 warps, warp w -> subpartition (w&3) rows, col-half (w>>2)
    uint32_t regs[64];
    const int ch = wid >> 2, sp = wid & 3;
    ldtm32(regs, tmem + ch * 64);
    ldtm32(regs + 32, tmem + ch * 64 + 32);
    asm volatile("tcgen05.wait::ld.sync.aligned;" ::: "memory");
    asm volatile("tcgen05.fence::before_thread_sync;" ::: "memory");
    const int r = row0 + sp * 32 + lane;
    const int cb = col0 + ch * 64;
    if (MODE == 2) {
        __half* C = (__half*)Cout;
#pragma unroll
        for (int j = 0; j < 64; j += 2) {
            __half2 h2 = __floats2half2_rn(__uint_as_float(regs[j]), __uint_as_float(regs[j + 1]));
            *(__half2*)(C + (size_t)r * ldc + cb + j) = h2;
        }
    } else if (MODE == 3) {
        // fused LSTM pointwise: 16 interleaved (i,f,g,o) quadruples per thread
        const int tc = text[r * Sq + step];
        const float* yp = addsrc + (size_t)r * ldadd + addoff + cb;
        const float* we = g_We + (size_t)tc * NG + cb;
        const int j0 = cb >> 2;
#pragma unroll
        for (int u = 0; u < 16; u++) {
            float4 ya = *(const float4*)(yp + u * 4);
            float4 wa = *(const float4*)(we + u * 4);
            float gi = __uint_as_float(regs[u * 4 + 0]) + ya.x + wa.x;
            float gf = __uint_as_float(regs[u * 4 + 1]) + ya.y + wa.y;
            float gg = __uint_as_float(regs[u * 4 + 2]) + ya.z + wa.z;
            float go = __uint_as_float(regs[u * 4 + 3]) + ya.w + wa.w;
            const int idx = r * Hq + j0 + u;
            float cprev = g_c[idx];
            float c2 = fast_sigmoid(gf) * cprev + fast_sigmoid(gi) * fast_tanh(gg);
            float h2 = fast_sigmoid(go) * fast_tanh(c2);
            g_c[idx] = c2;
            g_h[idx] = h2;
            split2(h2, &g_h_hi[idx], &g_h_lo[idx]);
        }
    } else {
        float* C = (float*)Cout;
#pragma unroll
        for (int j = 0; j < 64; j += 4) {
            float4 v;
            v.x = __uint_as_float(regs[j]);
            v.y = __uint_as_float(regs[j + 1]);
            v.z = __uint_as_float(regs[j + 2]);
            v.w = __uint_as_float(regs[j + 3]);
            *(float4*)(C + (size_t)r * ldc + cb + j) = v;
        }
    }
    __syncthreads();
    if (wid == 0) {
        if (lane == 0)
            asm volatile("mbarrier.inval.shared.b64 [%0];" :: "r"(mbar) : "memory");
        asm volatile("tcgen05.relinquish_alloc_permit.cta_group::1.sync.aligned;");
        asm volatile("tcgen05.dealloc.cta_group::1.sync.aligned.b32 %0, %1;" :: "r"(tmem), "r"(128));
    }
#else
    // -------- SIMT fallback (plain sm_103 compilation unit): correct path ----
    __shared__ float As[16][128];
    __shared__ float Bs[16][128];
    const int tid = threadIdx.x;
    const int tx = tid & 15, ty = tid >> 4;
    const int row0 = blockIdx.y * 128, col0 = blockIdx.x * 128;

    float acc[8][8];
#pragma unroll
    for (int i = 0; i < 8; i++)
#pragma unroll
        for (int j = 0; j < 8; j++) acc[i][j] = 0.f;

    for (int k0 = 0; k0 < K; k0 += 16) {
        int r = tid >> 1;
        int kk = (tid & 1) << 3;
        {
            uint4 uh = *(const uint4*)(Ahi + (size_t)(row0 + r) * K + k0 + kk);
            uint4 ul = *(const uint4*)(Alo + (size_t)(row0 + r) * K + k0 + kk);
            const __nv_bfloat16* hh = (const __nv_bfloat16*)&uh;
            const __nv_bfloat16* ll = (const __nv_bfloat16*)&ul;
#pragma unroll
            for (int j = 0; j < 8; j++)
                As[kk + j][r] = __bfloat162float(hh[j]) + __bfloat162float(ll[j]);
        }
        {
            uint4 uh = *(const uint4*)(Bhi + (size_t)(col0 + r) * K + k0 + kk);
            uint4 ul = *(const uint4*)(Blo + (size_t)(col0 + r) * K + k0 + kk);
            const __nv_bfloat16* hh = (const __nv_bfloat16*)&uh;
            const __nv_bfloat16* ll = (const __nv_bfloat16*)&ul;
#pragma unroll
            for (int j = 0; j < 8; j++)
                Bs[kk + j][r] = __bfloat162float(hh[j]) + __bfloat162float(ll[j]);
        }
        __syncthreads();
#pragma unroll
        for (int k = 0; k < 16; k++) {
            float a[8], b[8];
#pragma unroll
            for (int q = 0; q < 2; q++) {
                *(float4*)(&a[q * 4]) = *(const float4*)(&As[k][ty * 8 + q * 4]);
                *(float4*)(&b[q * 4]) = *(const float4*)(&Bs[k][tx * 8 + q * 4]);
            }
#pragma unroll
            for (int i = 0; i < 8; i++)
#pragma unroll
                for (int j = 0; j < 8; j++)
                    acc[i][j] = fmaf(a[i], b[j], acc[i][j]);
        }
        __syncthreads();
    }
#pragma unroll
    for (int i = 0; i < 8; i++) {
        int r = row0 + ty * 8 + i;
        int cbase = col0 + tx * 8;
        if (MODE == 3) {
            const int tc = text[r * Sq + step];
#pragma unroll
            for (int u = 0; u < 2; u++) {
                int cb4 = cbase + u * 4;
                float gi = acc[i][u * 4 + 0] + addsrc[(size_t)r * ldadd + addoff + cb4 + 0] + g_We[(size_t)tc * NG + cb4 + 0];
                float gf = acc[i][u * 4 + 1] + addsrc[(size_t)r * ldadd + addoff + cb4 + 1] + g_We[(size_t)tc * NG + cb4 + 1];
                float gg = acc[i][u * 4 + 2] + addsrc[(size_t)r * ldadd + addoff + cb4 + 2] + g_We[(size_t)tc * NG + cb4 + 2];
                float go = acc[i][u * 4 + 3] + addsrc[(size_t)r * ldadd + addoff + cb4 + 3] + g_We[(size_t)tc * NG + cb4 + 3];
                const int idx = r * Hq + (cb4 >> 2);
                float cprev = g_c[idx];
                float c2 = fast_sigmoid(gf) * cprev + fast_sigmoid(gi) * fast_tanh(gg);
                float h2 = fast_sigmoid(go) * fast_tanh(c2);
                g_c[idx] = c2;
                g_h[idx] = h2;
                split2(h2, &g_h_hi[idx], &g_h_lo[idx]);
            }
        } else {
#pragma unroll
            for (int j = 0; j < 8; j++) {
                int c = cbase + j;
                float v = acc[i][j];
                if (MODE == 2)
                    ((__half*)Cout)[(size_t)r * ldc + c] = __float2half(v);
                else
                    ((float*)Cout)[(size_t)r * ldc + c] = v;
            }
        }
    }
#endif
}

// ---------------- fused attention: e -> softmax -> ctx (hi/lo) --------------
__global__ __launch_bounds__(256)
void attn_kernel(const float* __restrict__ b_hid, const float* __restrict__ w_score) {
    __shared__ float hp_s[Hq];
    __shared__ float ws[Hq];
    __shared__ float e_s[Tq];
    const int b = blockIdx.x, tid = threadIdx.x, warp = tid >> 5, lane = tid & 31;

    for (int i = tid; i < Hq; i += 256) {
        hp_s[i] = g_y1[b * NC1 + i] + b_hid[i];   // hp part of merged GEMM1
        ws[i] = w_score[i];
    }
    __syncthreads();

    const __half* fb = g_feat + (size_t)b * Tq * Hq;
    for (int t = warp; t < Tq; t += 8) {
        const __half* fr = fb + (size_t)t * Hq;
        float s = 0.f;
#pragma unroll
        for (int j = 0; j < 2; j++) {
            int h0 = lane * 8 + j * 256;
            uint4 u = *(const uint4*)(fr + h0);
            __half2* hv = (__half2*)&u;
#pragma unroll
            for (int q = 0; q < 4; q++) {
                float2 f = __half22float2(hv[q]);
                int h = h0 + q * 2;
                s += tanh_approx(f.x + hp_s[h]) * ws[h];
                s += tanh_approx(f.y + hp_s[h + 1]) * ws[h + 1];
            }
        }
#pragma unroll
        for (int o = 16; o; o >>= 1) s += __shfl_xor_sync(0xffffffffu, s, o);
        if (lane == 0) e_s[t] = s;
    }
    __syncthreads();

    if (warp == 0) {
        float v0 = e_s[lane], v1 = e_s[lane + 32], v2 = e_s[lane + 64], v3 = e_s[lane + 96];
        float m = fmaxf(fmaxf(v0, v1), fmaxf(v2, v3));
#pragma unroll
        for (int o = 16; o; o >>= 1) m = fmaxf(m, __shfl_xor_sync(0xffffffffu, m, o));
        float x0 = __expf(v0 - m), x1 = __expf(v1 - m), x2 = __expf(v2 - m), x3 = __expf(v3 - m);
        float sum = x0 + x1 + x2 + x3;
#pragma unroll
        for (int o = 16; o; o >>= 1) sum += __shfl_xor_sync(0xffffffffu, sum, o);
        float inv = __fdividef(1.f, sum);
        e_s[lane] = x0 * inv;      e_s[lane + 32] = x1 * inv;
        e_s[lane + 64] = x2 * inv; e_s[lane + 96] = x3 * inv;
    }
    __syncthreads();

    // ctx: 2 columns per thread from fp16 batch_H copy
    const __half* Hb = g_bH16 + (size_t)b * Tq * Iq;
    const int i2 = tid * 2;
    float a0 = 0.f, a1 = 0.f;
#pragma unroll 4
    for (int t = 0; t < Tq; t++) {
        __half2 v = *(const __half2*)(Hb + (size_t)t * Iq + i2);
        float2 f = __half22float2(v);
        float al = e_s[t];
        a0 = fmaf(al, f.x, a0);
        a1 = fmaf(al, f.y, a1);
    }
    split2(a0, &g_ctx_hi[b * Iq + i2], &g_ctx_lo[b * Iq + i2]);
    split2(a1, &g_ctx_hi[b * Iq + i2 + 1], &g_ctx_lo[b * Iq + i2 + 1]);
}

// ---------------- generator (one block per b) --------------------------------
__global__ __launch_bounds__(512)
void gen_kernel(const float* __restrict__ W_gen, const float* __restrict__ b_gen,
                float* __restrict__ out, int s) {
    __shared__ float hs[Hq];
    const int b = blockIdx.x, tid = threadIdx.x;
    hs[tid] = g_h[b * Hq + tid];
    __syncthreads();
    const int warp = tid >> 5, lane = tid & 31;
    for (int c = warp; c < Cq; c += 16) {
        const float* w = W_gen + (size_t)c * Hq;
        float sum = 0.f;
#pragma unroll 4
        for (int h = lane; h < Hq; h += 32) sum = fmaf(hs[h], w[h], sum);
#pragma unroll
        for (int o = 16; o; o >>= 1) sum += __shfl_xor_sync(0xffffffffu, sum, o);
        if (lane == 0) out[((size_t)b * Sq + s) * Cq + c] = sum + b_gen[c];
    }
}

// ---------------- launch ----------------------------------------------------
extern "C" void kernel_launch(void* const* d_in, const int* in_sizes, int n_in,
                              void* d_out, int out_size) {
    const float* batch_H = (const float*)d_in[0];
    const int*   text    = (const int*)d_in[1];
    const float* W_feat  = (const float*)d_in[2];
    const float* W_hid   = (const float*)d_in[3];
    const float* b_hid   = (const float*)d_in[4];
    const float* w_score = (const float*)d_in[5];
    const float* W_ih    = (const float*)d_in[6];
    const float* W_hh    = (const float*)d_in[7];
    const float* b_ih    = (const float*)d_in[8];
    const float* b_hh    = (const float*)d_in[9];
    const float* W_gen   = (const float*)d_in[10];
    const float* b_gen   = (const float*)d_in[11];
    float* out = (float*)d_out;

    __nv_bfloat16 *p_bH_hi, *p_bH_lo, *p_h_hi, *p_h_lo, *p_ctx_hi, *p_ctx_lo;
    __nv_bfloat16 *p_Wc_hi, *p_Wc_lo, *p_Wih_hi, *p_Wih_lo, *p_Wf_hi, *p_Wf_lo;
    float *p_y1;
    __half* p_feat;
    cudaGetSymbolAddress((void**)&p_bH_hi, g_bH_hi);
    cudaGetSymbolAddress((void**)&p_bH_lo, g_bH_lo);
    cudaGetSymbolAddress((void**)&p_h_hi, g_h_hi);
    cudaGetSymbolAddress((void**)&p_h_lo, g_h_lo);
    cudaGetSymbolAddress((void**)&p_ctx_hi, g_ctx_hi);
    cudaGetSymbolAddress((void**)&p_ctx_lo, g_ctx_lo);
    cudaGetSymbolAddress((void**)&p_Wc_hi, g_Wc_hi);
    cudaGetSymbolAddress((void**)&p_Wc_lo, g_Wc_lo);
    cudaGetSymbolAddress((void**)&p_Wih_hi, g_Wih_hi);
    cudaGetSymbolAddress((void**)&p_Wih_lo, g_Wih_lo);
    cudaGetSymbolAddress((void**)&p_Wf_hi, g_Wf_hi);
    cudaGetSymbolAddress((void**)&p_Wf_lo, g_Wf_lo);
    cudaGetSymbolAddress((void**)&p_y1, g_y1);
    cudaGetSymbolAddress((void**)&p_feat, g_feat);

    cudaFuncSetAttribute(gemm_tc<0>, cudaFuncAttributeMaxDynamicSharedMemorySize, GEMM_SMEM);
    cudaFuncSetAttribute(gemm_tc<2>, cudaFuncAttributeMaxDynamicSharedMemorySize, GEMM_SMEM);
    cudaFuncSetAttribute(gemm_tc<3>, cudaFuncAttributeMaxDynamicSharedMemorySize, GEMM_SMEM);

    prep_bh<<<((size_t)Bq * Tq * Iq) / (256 * 8), 256>>>(batch_H);
    prep_w<<<(PREPW_ITEMS + 255) / 256, 256>>>(W_hid, W_hh, W_ih, W_feat, b_ih, b_hh);

    // feat = batch_H @ W_feat^T  [65536 x 512], K = 512, fp16 out
    gemm_tc<2><<<dim3(Hq / 128, (Bq * Tq) / 128), 256, GEMM_SMEM>>>(
        p_bH_hi, p_bH_lo, p_Wf_hi, p_Wf_lo, Iq, p_feat, Hq, nullptr, 0, 0, nullptr, 0);

    for (int s = 0; s < Sq; s++) {
        // y1 = h @ [W_hid; W_hh(interleaved)]^T  [512 x 2560], K = 512
        gemm_tc<0><<<dim3(NC1 / 128, Bq / 128), 256, GEMM_SMEM>>>(
            p_h_hi, p_h_lo, p_Wc_hi, p_Wc_lo, Hq, p_y1, NC1, nullptr, 0, 0, nullptr, 0);

        attn_kernel<<<Bq, 256>>>(b_hid, w_score);

        // gates = ctx @ W_ih(interleaved)^T + y1[:, 512:] + We[text], fused LSTM
        gemm_tc<3><<<dim3(NG / 128, Bq / 128), 256, GEMM_SMEM>>>(
            p_ctx_hi, p_ctx_lo, p_Wih_hi, p_Wih_lo, Iq, nullptr, 0, p_y1, NC1, Hq, text, s);

        gen_kernel<<<Bq, 512>>>(W_gen, b_gen, out, s);
    }
}

// round 7
// speedup vs baseline: 2.8095x; 1.0060x over previous
#include <cuda_runtime.h>
#include <cuda_fp16.h>
#include <cuda_bf16.h>
#include <cstdint>

// Problem dims (fixed)
#define Bq 512
#define Tq 128
#define Iq 512
#define Hq 512
#define Cq 97
#define Sq 26
#define NC1 2560   // hp(512) + interleaved gates_h(2048)
#define NG  2048   // 4H interleaved: col 4*j+g = gate g of unit j

#if defined(__CUDA_ARCH_FEAT_SM103_ALL) || defined(__CUDA_ARCH_FEAT_SM100_ALL)
#define HAS_TCGEN05 1
#else
#define HAS_TCGEN05 0
#endif

// ---------------- scratch (static device globals; no allocations) ----------
__device__ __align__(16) __nv_bfloat16 g_bH_hi[(size_t)Bq * Tq * Iq];
__device__ __align__(16) __nv_bfloat16 g_bH_lo[(size_t)Bq * Tq * Iq];
__device__ __align__(16) __half        g_bH16[(size_t)Bq * Tq * Iq];
__device__ __align__(16) __half        g_feat[(size_t)Bq * Tq * Hq];
__device__ __align__(16) float         g_h[Bq * Hq];
__device__ __align__(16) float         g_c[Bq * Hq];
__device__ __align__(16) __nv_bfloat16 g_h_hi[Bq * Hq];
__device__ __align__(16) __nv_bfloat16 g_h_lo[Bq * Hq];
__device__ __align__(16) __nv_bfloat16 g_ctx_hi[Bq * Iq];
__device__ __align__(16) __nv_bfloat16 g_ctx_lo[Bq * Iq];
__device__ __align__(16) float         g_y1[Bq * NC1];
__device__ __align__(16) __nv_bfloat16 g_Wc_hi[NC1 * Hq];
__device__ __align__(16) __nv_bfloat16 g_Wc_lo[NC1 * Hq];
__device__ __align__(16) __nv_bfloat16 g_Wih_hi[NG * Iq];
__device__ __align__(16) __nv_bfloat16 g_Wih_lo[NG * Iq];
__device__ __align__(16) __nv_bfloat16 g_Wf_hi[Hq * Iq];
__device__ __align__(16) __nv_bfloat16 g_Wf_lo[Hq * Iq];
__device__ __align__(16) float         g_We[Cq * NG];  // interleaved one-hot col + biases

// ---------------- helpers ---------------------------------------------------
__device__ __forceinline__ float fast_sigmoid(float x) {
    return __fdividef(1.f, 1.f + __expf(-x));
}
__device__ __forceinline__ float fast_tanh(float x) {
    float xc = fminf(fmaxf(x, -15.f), 15.f);
    float e = __expf(2.f * xc);
    return __fdividef(e - 1.f, e + 1.f);
}
__device__ __forceinline__ float tanh_approx(float x) {
    float y;
    asm("tanh.approx.f32 %0, %1;" : "=f"(y) : "f"(x));
    return y;
}
__device__ __forceinline__ void split2(float a, __nv_bfloat16* hi, __nv_bfloat16* lo) {
    __nv_bfloat16 h = __float2bfloat16(a);
    *hi = h;
    *lo = __float2bfloat16(a - __bfloat162float(h));
}
__device__ __forceinline__ uint32_t s2u(const void* p) {
    uint32_t a;
    asm("{ .reg .u64 t; cvta.to.shared.u64 t, %1; cvt.u32.u64 %0, t; }" : "=r"(a) : "l"(p));
    return a;
}
__device__ __forceinline__ void cpa16(uint32_t s, const void* g) {
    asm volatile("cp.async.cg.shared.global [%0], [%1], 16;" :: "r"(s), "l"(g));
}

#if HAS_TCGEN05
__device__ __forceinline__ uint32_t elect1() {
    uint32_t p;
    asm volatile("{ .reg .pred p; elect.sync _|p, 0xFFFFFFFF; selp.b32 %0, 1, 0, p; }" : "=r"(p));
    return p;
}
__device__ __forceinline__ void mbar_wait(uint32_t a, uint32_t ph) {
    asm volatile(
        "{\n\t.reg .pred P;\n"
        "LW%=:\n\t"
        "mbarrier.try_wait.parity.acquire.cta.shared::cta.b64 P, [%0], %1, 0x989680;\n\t"
        "@!P bra.uni LW%=;\n\t}"
        :: "r"(a), "r"(ph) : "memory");
}
__device__ __forceinline__ void mma_ss(uint32_t d, uint64_t a, uint64_t b, uint32_t idesc, bool en) {
    uint32_t e = en ? 1u : 0u;
    asm volatile(
        "{\n\t.reg .pred p;\n\t"
        "setp.ne.u32 p, %5, 0;\n\t"
        "tcgen05.mma.cta_group::1.kind::f16 [%0], %1, %2, %3, {%4, %4, %4, %4}, p;\n\t}"
        :: "r"(d), "l"(a), "l"(b), "r"(idesc), "r"(0u), "r"(e) : "memory");
}
__device__ __forceinline__ void ldtm32(uint32_t* r, uint32_t a) {
    asm volatile(
        "tcgen05.ld.sync.aligned.32x32b.x32.b32 "
        "{%0, %1, %2, %3, %4, %5, %6, %7, %8, %9, %10, %11, %12, %13, %14, %15, "
        "%16, %17, %18, %19, %20, %21, %22, %23, %24, %25, %26, %27, %28, %29, %30, %31}, [%32];"
        : "=r"(r[0]), "=r"(r[1]), "=r"(r[2]), "=r"(r[3]), "=r"(r[4]), "=r"(r[5]), "=r"(r[6]), "=r"(r[7]),
          "=r"(r[8]), "=r"(r[9]), "=r"(r[10]), "=r"(r[11]), "=r"(r[12]), "=r"(r[13]), "=r"(r[14]), "=r"(r[15]),
          "=r"(r[16]), "=r"(r[17]), "=r"(r[18]), "=r"(r[19]), "=r"(r[20]), "=r"(r[21]), "=r"(r[22]), "=r"(r[23]),
          "=r"(r[24]), "=r"(r[25]), "=r"(r[26]), "=r"(r[27]), "=r"(r[28]), "=r"(r[29]), "=r"(r[30]), "=r"(r[31])
        : "r"(a));
}
#endif

static constexpr uint64_t DESCBASE =
    (uint64_t(2) << 61) | (uint64_t(1) << 46) | (uint64_t(64) << 32) | (uint64_t(1) << 16); // SW128 K-major

// stage layout: A_hi 16KB | A_lo 16KB | B_hi TN*128 | B_lo TN*128
template <int TN> struct GP {
    static constexpr int BT = TN * 128;                 // one B matrix bytes
    static constexpr int STAGE = 32768 + 2 * BT;
    static constexpr int SMEM = 2 * STAGE + 1024;
    static constexpr uint32_t IDESC = 0x8000490u | ((TN / 8) << 17);
};

// ---------------- prep kernels ----------------------------------------------
__global__ void prep_bh(const float* __restrict__ bH) {
    size_t i0 = ((size_t)blockIdx.x * blockDim.x + threadIdx.x) * 8;
    float4 v0 = *(const float4*)(bH + i0);
    float4 v1 = *(const float4*)(bH + i0 + 4);
    float f[8] = {v0.x, v0.y, v0.z, v0.w, v1.x, v1.y, v1.z, v1.w};
    __nv_bfloat16 hi[8], lo[8];
    __half h16[8];
#pragma unroll
    for (int j = 0; j < 8; j++) {
        split2(f[j], &hi[j], &lo[j]);
        h16[j] = __float2half(f[j]);
    }
    *(uint4*)(g_bH_hi + i0) = *(const uint4*)hi;
    *(uint4*)(g_bH_lo + i0) = *(const uint4*)lo;
    *(uint4*)(g_bH16 + i0)  = *(const uint4*)h16;
}
__global__ void prep_w(const float* __restrict__ W_hid, const float* __restrict__ W_hh,
                       const float* __restrict__ W_ih, const float* __restrict__ W_feat,
                       const float* __restrict__ b_ih, const float* __restrict__ b_hh) {
    int idx = blockIdx.x * blockDim.x + threadIdx.x;
    if (idx < NC1 * Hq) {                          // Wc = [W_hid ; interleaved W_hh]
        int j = idx >> 9, k = idx & 511;
        float v;
        if (j < Hq) v = W_hid[j * Hq + k];
        else {
            int jj = j - Hq, j2 = jj >> 2, gg = jj & 3;
            v = W_hh[(size_t)(gg * Hq + j2) * Hq + k];
        }
        split2(v, &g_Wc_hi[idx], &g_Wc_lo[idx]);
        return;
    }
    idx -= NC1 * Hq;
    if (idx < NG * Iq) {                           // interleaved W_ih[:, :I]
        int j = idx >> 9, k = idx & 511;
        int j2 = j >> 2, gg = j & 3;
        split2(W_ih[(size_t)(gg * Hq + j2) * (Iq + Cq) + k], &g_Wih_hi[idx], &g_Wih_lo[idx]);
        return;
    }
    idx -= NG * Iq;
    if (idx < Hq * Iq) {                           // W_feat
        split2(W_feat[idx], &g_Wf_hi[idx], &g_Wf_lo[idx]);
        return;
    }
    idx -= Hq * Iq;
    if (idx < Cq * NG) {                           // We[c][j] interleaved + biases
        int c = idx / NG, j = idx - c * NG;
        int j2 = j >> 2, gg = j & 3;
        int rr = gg * Hq + j2;
        g_We[idx] = W_ih[(size_t)rr * (Iq + Cq) + Iq + c] + b_ih[rr] + b_hh[rr];
        return;
    }
    idx -= Cq * NG;
    if (idx < Bq * Hq) {                           // init state
        g_c[idx] = 0.f;
        g_h[idx] = 0.f;
        g_h_hi[idx] = __float2bfloat16(0.f);
        g_h_lo[idx] = __float2bfloat16(0.f);
    }
}
static constexpr int PREPW_ITEMS = NC1 * Hq + NG * Iq + Hq * Iq + Cq * NG + Bq * Hq;

// ---------------- split-bf16 GEMM: C[M=128,TN] = A[128,K] @ B[TN,K]^T --------
// MODE 0: fp32 out. MODE 2: fp16 out. MODE 3: fused LSTM epilogue (gate-interleaved).
template <int MODE, int TN>
__global__ __launch_bounds__(256)
void gemm_tc(const __nv_bfloat16* __restrict__ Ahi, const __nv_bfloat16* __restrict__ Alo,
             const __nv_bfloat16* __restrict__ Bhi, const __nv_bfloat16* __restrict__ Blo,
             int K, void* Cout, int ldc,
             const float* __restrict__ addsrc, int ldadd, int addoff,
             const int* __restrict__ text, int step) {
#if HAS_TCGEN05
    extern __shared__ char dsm[];
    __shared__ uint32_t s_tmem[2];
    __shared__ __align__(8) uint64_t s_mbar;
    const int tid = threadIdx.x, wid = tid >> 5, lane = tid & 31;
    const int row0 = blockIdx.y * 128, col0 = blockIdx.x * TN;

    uint32_t ctrl = s2u(s_tmem);
    uint32_t mbar = s2u(&s_mbar);
    if (wid == 0)
        asm volatile("tcgen05.alloc.cta_group::1.sync.aligned.shared::cta.b32 [%0], %1;"
                     :: "r"(ctrl), "r"(TN) : "memory");
    if (tid == 0)
        asm volatile("mbarrier.init.shared.b64 [%0], %1;" :: "r"(mbar), "r"(1) : "memory");
    __syncthreads();
    const uint32_t tmem = s_tmem[0];

    const uint32_t tile = (s2u(dsm) + 1023u) & ~1023u;
    const size_t aBase = (size_t)row0 * K;
    const size_t bBase = (size_t)col0 * K;
    const int nchunk = K >> 6;
    constexpr int BPC = TN / 32;   // B 16B pieces per thread per matrix

    auto load_chunk = [&](int c, int st) {
        uint32_t base = tile + st * GP<TN>::STAGE;
        size_t kofs = (size_t)c * 64;
#pragma unroll
        for (int s4 = 0; s4 < 4; s4++) {           // A: 128 rows
            int v = tid + (s4 << 8);
            int r = v >> 3;
            int c8 = (v & 7) << 3;
            uint32_t so = (uint32_t)(r * 128 + c8 * 2);
            so ^= (so >> 3) & 0x70;
            size_t ga = aBase + (size_t)r * K + c8 + kofs;
            cpa16(base + so,         Ahi + ga);
            cpa16(base + 16384 + so, Alo + ga);
        }
#pragma unroll
        for (int s4 = 0; s4 < BPC; s4++) {          // B: TN rows
            int v = tid + (s4 << 8);
            int r = v >> 3;
            int c8 = (v & 7) << 3;
            uint32_t so = (uint32_t)(r * 128 + c8 * 2);
            so ^= (so >> 3) & 0x70;
            size_t gb = bBase + (size_t)r * K + c8 + kofs;
            cpa16(base + 32768 + so,                Bhi + gb);
            cpa16(base + 32768 + GP<TN>::BT + so,   Blo + gb);
        }
        asm volatile("cp.async.commit_group;" ::: "memory");
    };

    load_chunk(0, 0);

    for (int c = 0; c < nchunk; c++) {
        const int st = c & 1;
        if (c >= 1) mbar_wait(mbar, (uint32_t)((c - 1) & 1));
        if (c + 1 < nchunk) {
            load_chunk(c + 1, st ^ 1);
            asm volatile("cp.async.wait_group 1;" ::: "memory");
        } else {
            asm volatile("cp.async.wait_group 0;" ::: "memory");
        }
        asm volatile("fence.proxy.async.shared::cta;" ::: "memory");
        __syncthreads();

        if (wid == 0 && elect1()) {
            uint32_t base = tile + st * GP<TN>::STAGE;
            const uint64_t dA0 = DESCBASE | ((base >> 4) & 0x3FFF);
            const uint64_t dA1 = DESCBASE | (((base + 16384) >> 4) & 0x3FFF);
            const uint64_t dB0 = DESCBASE | (((base + 32768) >> 4) & 0x3FFF);
            const uint64_t dB1 = DESCBASE | (((base + 32768 + GP<TN>::BT) >> 4) & 0x3FFF);
#pragma unroll
            for (int ks = 0; ks < 4; ks++)
                mma_ss(tmem, dA0 + ks * 2, dB0 + ks * 2, GP<TN>::IDESC, !(c == 0 && ks == 0));
#pragma unroll
            for (int ks = 0; ks < 4; ks++)
                mma_ss(tmem, dA0 + ks * 2, dB1 + ks * 2, GP<TN>::IDESC, true);
#pragma unroll
            for (int ks = 0; ks < 4; ks++)
                mma_ss(tmem, dA1 + ks * 2, dB0 + ks * 2, GP<TN>::IDESC, true);
            asm volatile(
                "tcgen05.commit.cta_group::1.mbarrier::arrive::one.shared::cluster.b64 [%0];"
                :: "r"(mbar) : "memory");
        }
    }
    mbar_wait(mbar, (uint32_t)((nchunk - 1) & 1));
    asm volatile("tcgen05.fence::after_thread_sync;" ::: "memory");

    // epilogue: 8 warps: sp = wid&3 rows, ch = wid>>2 col half (TN/2 cols each)
    constexpr int HC = TN / 2;
    uint32_t regs[HC];
    const int ch = wid >> 2, sp = wid & 3;
    ldtm32(regs, tmem + ch * HC);
    if (TN == 128) ldtm32(regs + 32, tmem + ch * HC + 32);
    asm volatile("tcgen05.wait::ld.sync.aligned;" ::: "memory");
    asm volatile("tcgen05.fence::before_thread_sync;" ::: "memory");
    const int r = row0 + sp * 32 + lane;
    const int cb = col0 + ch * HC;
    if (MODE == 2) {
        __half* C = (__half*)Cout;
#pragma unroll
        for (int j = 0; j < HC; j += 2) {
            __half2 h2 = __floats2half2_rn(__uint_as_float(regs[j]), __uint_as_float(regs[j + 1]));
            *(__half2*)(C + (size_t)r * ldc + cb + j) = h2;
        }
    } else if (MODE == 3) {
        const int tc = text[r * Sq + step];
        const float* yp = addsrc + (size_t)r * ldadd + addoff + cb;
        const float* we = g_We + (size_t)tc * NG + cb;
        const int j0 = cb >> 2;
#pragma unroll
        for (int u = 0; u < HC / 4; u++) {
            float4 ya = *(const float4*)(yp + u * 4);
            float4 wa = *(const float4*)(we + u * 4);
            float gi = __uint_as_float(regs[u * 4 + 0]) + ya.x + wa.x;
            float gf = __uint_as_float(regs[u * 4 + 1]) + ya.y + wa.y;
            float gg = __uint_as_float(regs[u * 4 + 2]) + ya.z + wa.z;
            float go = __uint_as_float(regs[u * 4 + 3]) + ya.w + wa.w;
            const int idx = r * Hq + j0 + u;
            float cprev = g_c[idx];
            float c2 = fast_sigmoid(gf) * cprev + fast_sigmoid(gi) * fast_tanh(gg);
            float h2 = fast_sigmoid(go) * fast_tanh(c2);
            g_c[idx] = c2;
            g_h[idx] = h2;
            split2(h2, &g_h_hi[idx], &g_h_lo[idx]);
        }
    } else {
        float* C = (float*)Cout;
#pragma unroll
        for (int j = 0; j < HC; j += 4) {
            float4 v;
            v.x = __uint_as_float(regs[j]);
            v.y = __uint_as_float(regs[j + 1]);
            v.z = __uint_as_float(regs[j + 2]);
            v.w = __uint_as_float(regs[j + 3]);
            *(float4*)(C + (size_t)r * ldc + cb + j) = v;
        }
    }
    __syncthreads();
    if (wid == 0) {
        if (lane == 0)
            asm volatile("mbarrier.inval.shared.b64 [%0];" :: "r"(mbar) : "memory");
        asm volatile("tcgen05.relinquish_alloc_permit.cta_group::1.sync.aligned;");
        asm volatile("tcgen05.dealloc.cta_group::1.sync.aligned.b32 %0, %1;" :: "r"(tmem), "r"(TN));
    }
#else
    // -------- SIMT fallback (plain sm_103 unit): simple + correct, never hot --
    const int tid = threadIdx.x;
    const int row0 = blockIdx.y * 128, col0 = blockIdx.x * TN;
    if (MODE == 3) {
        for (int q = tid; q < 128 * (TN / 4); q += 256) {
            int r = row0 + q / (TN / 4);
            int c4 = col0 + (q % (TN / 4)) * 4;
            const int tc = text[r * Sq + step];
            float g4[4];
#pragma unroll
            for (int gg = 0; gg < 4; gg++) {
                float acc = 0.f;
                for (int k = 0; k < K; k++) {
                    float av = __bfloat162float(Ahi[(size_t)r * K + k]) + __bfloat162float(Alo[(size_t)r * K + k]);
                    float bv = __bfloat162float(Bhi[(size_t)(c4 + gg) * K + k]) + __bfloat162float(Blo[(size_t)(c4 + gg) * K + k]);
                    acc = fmaf(av, bv, acc);
                }
                g4[gg] = acc + addsrc[(size_t)r * ldadd + addoff + c4 + gg] + g_We[(size_t)tc * NG + c4 + gg];
            }
            const int idx = r * Hq + (c4 >> 2);
            float cprev = g_c[idx];
            float c2 = fast_sigmoid(g4[1]) * cprev + fast_sigmoid(g4[0]) * fast_tanh(g4[2]);
            float h2 = fast_sigmoid(g4[3]) * fast_tanh(c2);
            g_c[idx] = c2;
            g_h[idx] = h2;
            split2(h2, &g_h_hi[idx], &g_h_lo[idx]);
        }
    } else {
        for (int e = tid; e < 128 * TN; e += 256) {
            int r = row0 + e / TN, cc = col0 + e % TN;
            float acc = 0.f;
            for (int k = 0; k < K; k++) {
                float av = __bfloat162float(Ahi[(size_t)r * K + k]) + __bfloat162float(Alo[(size_t)r * K + k]);
                float bv = __bfloat162float(Bhi[(size_t)cc * K + k]) + __bfloat162float(Blo[(size_t)cc * K + k]);
                acc = fmaf(av, bv, acc);
            }
            if (MODE == 2)
                ((__half*)Cout)[(size_t)r * ldc + cc] = __float2half(acc);
            else
                ((float*)Cout)[(size_t)r * ldc + cc] = acc;
        }
    }
#endif
}

// ---- fused attention + previous-step generator (one block per b, 512 thr) ---
__global__ __launch_bounds__(512)
void attn_kernel(const float* __restrict__ b_hid, const float* __restrict__ w_score,
                 const float* __restrict__ W_gen, const float* __restrict__ b_gen,
                 float* __restrict__ out, int s) {
    __shared__ float hp_s[Hq];
    __shared__ float ws[Hq];
    __shared__ float hs[Hq];
    __shared__ float e_s[Tq];
    __shared__ float2 cpart[2][256];
    const int b = blockIdx.x, tid = threadIdx.x, warp = tid >> 5, lane = tid & 31;

    hp_s[tid] = g_y1[b * NC1 + tid] + b_hid[tid];
    ws[tid] = w_score[tid];
    hs[tid] = g_h[b * Hq + tid];
    __syncthreads();

    // generator for step s-1 (h unchanged since last gemm3)
    if (s > 0) {
        for (int c = warp; c < Cq; c += 16) {
            const float* w = W_gen + (size_t)c * Hq;
            float sum = 0.f;
#pragma unroll 4
            for (int h = lane; h < Hq; h += 32) sum = fmaf(hs[h], w[h], sum);
#pragma unroll
            for (int o = 16; o; o >>= 1) sum += __shfl_xor_sync(0xffffffffu, sum, o);
            if (lane == 0) out[((size_t)b * Sq + (s - 1)) * Cq + c] = sum + b_gen[c];
        }
    }

    // e[t] = sum_h tanh(feat + hp) * ws   (16 warps x 8 t each)
    const __half* fb = g_feat + (size_t)b * Tq * Hq;
    for (int t = warp; t < Tq; t += 16) {
        const __half* fr = fb + (size_t)t * Hq;
        float sacc = 0.f;
#pragma unroll
        for (int j = 0; j < 2; j++) {
            int h0 = lane * 8 + j * 256;
            uint4 u = *(const uint4*)(fr + h0);
            __half2* hv = (__half2*)&u;
#pragma unroll
            for (int q = 0; q < 4; q++) {
                float2 f = __half22float2(hv[q]);
                int h = h0 + q * 2;
                sacc += tanh_approx(f.x + hp_s[h]) * ws[h];
                sacc += tanh_approx(f.y + hp_s[h + 1]) * ws[h + 1];
            }
        }
#pragma unroll
        for (int o = 16; o; o >>= 1) sacc += __shfl_xor_sync(0xffffffffu, sacc, o);
        if (lane == 0) e_s[t] = sacc;
    }
    __syncthreads();

    if (warp == 0) {
        float v0 = e_s[lane], v1 = e_s[lane + 32], v2 = e_s[lane + 64], v3 = e_s[lane + 96];
        float m = fmaxf(fmaxf(v0, v1), fmaxf(v2, v3));
#pragma unroll
        for (int o = 16; o; o >>= 1) m = fmaxf(m, __shfl_xor_sync(0xffffffffu, m, o));
        float x0 = __expf(v0 - m), x1 = __expf(v1 - m), x2 = __expf(v2 - m), x3 = __expf(v3 - m);
        float sum = x0 + x1 + x2 + x3;
#pragma unroll
        for (int o = 16; o; o >>= 1) sum += __shfl_xor_sync(0xffffffffu, sum, o);
        float inv = __fdividef(1.f, sum);
        e_s[lane] = x0 * inv;      e_s[lane + 32] = x1 * inv;
        e_s[lane + 64] = x2 * inv; e_s[lane + 96] = x3 * inv;
    }
    __syncthreads();

    // ctx: col pair p = tid&255, T split in halves across tid>>8
    const __half* Hb = g_bH16 + (size_t)b * Tq * Iq;
    const int p = tid & 255, hf = tid >> 8;
    const int i2 = p * 2;
    float a0 = 0.f, a1 = 0.f;
    const int t0 = hf * 64;
#pragma unroll 4
    for (int t = t0; t < t0 + 64; t++) {
        __half2 v = *(const __half2*)(Hb + (size_t)t * Iq + i2);
        float2 f = __half22float2(v);
        float al = e_s[t];
        a0 = fmaf(al, f.x, a0);
        a1 = fmaf(al, f.y, a1);
    }
    cpart[hf][p] = make_float2(a0, a1);
    __syncthreads();
    if (tid < 256) {
        float2 u0 = cpart[0][tid], u1 = cpart[1][tid];
        float c0 = u0.x + u1.x, c1 = u0.y + u1.y;
        const int j2 = tid * 2;
        split2(c0, &g_ctx_hi[b * Iq + j2], &g_ctx_lo[b * Iq + j2]);
        split2(c1, &g_ctx_hi[b * Iq + j2 + 1], &g_ctx_lo[b * Iq + j2 + 1]);
    }
}

// ---------------- generator (final step only) --------------------------------
__global__ __launch_bounds__(512)
void gen_kernel(const float* __restrict__ W_gen, const float* __restrict__ b_gen,
                float* __restrict__ out, int s) {
    __shared__ float hs[Hq];
    const int b = blockIdx.x, tid = threadIdx.x;
    hs[tid] = g_h[b * Hq + tid];
    __syncthreads();
    const int warp = tid >> 5, lane = tid & 31;
    for (int c = warp; c < Cq; c += 16) {
        const float* w = W_gen + (size_t)c * Hq;
        float sum = 0.f;
#pragma unroll 4
        for (int h = lane; h < Hq; h += 32) sum = fmaf(hs[h], w[h], sum);
#pragma unroll
        for (int o = 16; o; o >>= 1) sum += __shfl_xor_sync(0xffffffffu, sum, o);
        if (lane == 0) out[((size_t)b * Sq + s) * Cq + c] = sum + b_gen[c];
    }
}

// ---------------- launch ----------------------------------------------------
extern "C" void kernel_launch(void* const* d_in, const int* in_sizes, int n_in,
                              void* d_out, int out_size) {
    const float* batch_H = (const float*)d_in[0];
    const int*   text    = (const int*)d_in[1];
    const float* W_feat  = (const float*)d_in[2];
    const float* W_hid   = (const float*)d_in[3];
    const float* b_hid   = (const float*)d_in[4];
    const float* w_score = (const float*)d_in[5];
    const float* W_ih    = (const float*)d_in[6];
    const float* W_hh    = (const float*)d_in[7];
    const float* b_ih    = (const float*)d_in[8];
    const float* b_hh    = (const float*)d_in[9];
    const float* W_gen   = (const float*)d_in[10];
    const float* b_gen   = (const float*)d_in[11];
    float* out = (float*)d_out;

    __nv_bfloat16 *p_bH_hi, *p_bH_lo, *p_h_hi, *p_h_lo, *p_ctx_hi, *p_ctx_lo;
    __nv_bfloat16 *p_Wc_hi, *p_Wc_lo, *p_Wih_hi, *p_Wih_lo, *p_Wf_hi, *p_Wf_lo;
    float *p_y1;
    __half* p_feat;
    cudaGetSymbolAddress((void**)&p_bH_hi, g_bH_hi);
    cudaGetSymbolAddress((void**)&p_bH_lo, g_bH_lo);
    cudaGetSymbolAddress((void**)&p_h_hi, g_h_hi);
    cudaGetSymbolAddress((void**)&p_h_lo, g_h_lo);
    cudaGetSymbolAddress((void**)&p_ctx_hi, g_ctx_hi);
    cudaGetSymbolAddress((void**)&p_ctx_lo, g_ctx_lo);
    cudaGetSymbolAddress((void**)&p_Wc_hi, g_Wc_hi);
    cudaGetSymbolAddress((void**)&p_Wc_lo, g_Wc_lo);
    cudaGetSymbolAddress((void**)&p_Wih_hi, g_Wih_hi);
    cudaGetSymbolAddress((void**)&p_Wih_lo, g_Wih_lo);
    cudaGetSymbolAddress((void**)&p_Wf_hi, g_Wf_hi);
    cudaGetSymbolAddress((void**)&p_Wf_lo, g_Wf_lo);
    cudaGetSymbolAddress((void**)&p_y1, g_y1);
    cudaGetSymbolAddress((void**)&p_feat, g_feat);

    cudaFuncSetAttribute((const void*)gemm_tc<0, 64>,  cudaFuncAttributeMaxDynamicSharedMemorySize, GP<64>::SMEM);
    cudaFuncSetAttribute((const void*)gemm_tc<3, 64>,  cudaFuncAttributeMaxDynamicSharedMemorySize, GP<64>::SMEM);
    cudaFuncSetAttribute((const void*)gemm_tc<2, 128>, cudaFuncAttributeMaxDynamicSharedMemorySize, GP<128>::SMEM);

    prep_bh<<<((size_t)Bq * Tq * Iq) / (256 * 8), 256>>>(batch_H);
    prep_w<<<(PREPW_ITEMS + 255) / 256, 256>>>(W_hid, W_hh, W_ih, W_feat, b_ih, b_hh);

    // feat = batch_H @ W_feat^T  [65536 x 512], K = 512, fp16 out (TN=128)
    gemm_tc<2, 128><<<dim3(Hq / 128, (Bq * Tq) / 128), 256, GP<128>::SMEM>>>(
        p_bH_hi, p_bH_lo, p_Wf_hi, p_Wf_lo, Iq, p_feat, Hq, nullptr, 0, 0, nullptr, 0);

    for (int s = 0; s < Sq; s++) {
        // y1 = h @ [W_hid; W_hh(interleaved)]^T  [512 x 2560], K = 512 (TN=64, 160 CTAs)
        gemm_tc<0, 64><<<dim3(NC1 / 64, Bq / 128), 256, GP<64>::SMEM>>>(
            p_h_hi, p_h_lo, p_Wc_hi, p_Wc_lo, Hq, p_y1, NC1, nullptr, 0, 0, nullptr, 0);

        // attn + generator for step s-1
        attn_kernel<<<Bq, 512>>>(b_hid, w_score, W_gen, b_gen, out, s);

        // gates = ctx @ W_ih(interleaved)^T + y1[:, 512:] + We[text], fused LSTM (TN=64, 128 CTAs)
        gemm_tc<3, 64><<<dim3(NG / 64, Bq / 128), 256, GP<64>::SMEM>>>(
            p_ctx_hi, p_ctx_lo, p_Wih_hi, p_Wih_lo, Iq, nullptr, 0, p_y1, NC1, Hq, text, s);
    }
    gen_kernel<<<Bq, 512>>>(W_gen, b_gen, out, Sq - 1);
}